// round 13
// baseline (speedup 1.0000x reference)
#include <cuda_runtime.h>
#include <cstdint>
#include <cmath>

#define ZDIM 8192
#define NOUT 448

#define K0TOT 4736          // out0 padded K (592 groups)
#define K2TOT 2304          // out2 padded K (288 groups)
#define NG0   592
#define NG2   288

// ===================== device globals (no allocation) =====================
static __device__ float g_B0t[64 * K0TOT];         // out0 weights [w][k'], prescaled + tf32
static __device__ float g_B6t[64 * K2TOT];         // out2 weights [w][k'], prescaled + tf32
static __device__ float g_B3p[4096 * 64];          // out1 weights [n=(w*64+m)][u], tf32
static __device__ unsigned short g_desc0[NG0];     // group descriptors: type<<12|u<<6|v0
static __device__ unsigned short g_desc2[NG2];

// ===================== helpers =====================
__device__ __forceinline__ uint32_t rna(float f) {
    uint32_t r; asm("cvt.rna.tf32.f32 %0, %1;" : "=r"(r) : "f"(f)); return r;
}
__device__ __forceinline__ float u2f(uint32_t u) { return __uint_as_float(u); }
__device__ __forceinline__ uint32_t smem_u32(const void* p) {
    uint32_t a;
    asm("{ .reg .u64 t; cvta.to.shared.u64 t, %1; cvt.u32.u64 %0, t; }" : "=r"(a) : "l"(p));
    return a;
}
__device__ __forceinline__ void mma8(float* c, const uint32_t* a, const uint32_t* b) {
    asm volatile("mma.sync.aligned.m16n8k8.row.col.f32.tf32.tf32.f32 "
        "{%0,%1,%2,%3}, {%4,%5,%6,%7}, {%8,%9}, {%0,%1,%2,%3};"
        : "+f"(c[0]), "+f"(c[1]), "+f"(c[2]), "+f"(c[3])
        : "r"(a[0]), "r"(a[1]), "r"(a[2]), "r"(a[3]), "r"(b[0]), "r"(b[1]));
}
__device__ __forceinline__ void ldm_x4(uint32_t* r, uint32_t addr) {
    asm volatile("ldmatrix.sync.aligned.m8n8.x4.shared.b16 {%0,%1,%2,%3}, [%4];"
        : "=r"(r[0]), "=r"(r[1]), "=r"(r[2]), "=r"(r[3]) : "r"(addr));
}
__device__ __forceinline__ void ldm_x2(uint32_t* r, uint32_t addr) {
    asm volatile("ldmatrix.sync.aligned.m8n8.x2.shared.b16 {%0,%1}, [%2];"
        : "=r"(r[0]), "=r"(r[1]) : "r"(addr));
}
__device__ __forceinline__ int triq(int u, int v) {   // triu index, valid v>u
    return u * 63 - (u * (u - 1)) / 2 + (v - u - 1);
}

// ===================== setup kernels =====================
__global__ void init_tables_kernel() {
    int u = threadIdx.x;  // 64 threads
    if (u < 63) {
        int B = u >> 3, r = u & 7;
        int cum = 8 * (8 * B - (B * (B - 1)) / 2) + r * (8 - B);
        int cnt = 8 - B;
        for (int t = 0; t < cnt; ++t) {
            int v0 = 8 * (B + t);
            g_desc0[cum + t]       = (unsigned short)((0 << 12) | (u << 6) | v0);  // ss
            g_desc0[295 + cum + t] = (unsigned short)((2 << 12) | (u << 6) | v0);  // vdot
            g_desc2[cum + t]       = (unsigned short)((0 << 12) | (u << 6) | v0);  // cross
        }
    }
    if (u < 8) {
        g_desc0[287 + u] = (unsigned short)((1 << 12) | (8 * u));   // s^2 octet
        g_desc0[582 + u] = (unsigned short)((3 << 12) | (8 * u));   // |v|^2 octet
    }
    if (u < 2) g_desc0[590 + u] = (unsigned short)(4 << 12);        // pad
    if (u == 0) g_desc2[287] = (unsigned short)(4 << 12);           // pad
}

__global__ void prep_w_kernel(const float* __restrict__ w1, const float* __restrict__ w2,
                              const float* __restrict__ w3, const float* __restrict__ w4,
                              const float* __restrict__ w5, const float* __restrict__ w6,
                              float c1, float c2, float c5s, float c6s) {
    int i = blockIdx.x * blockDim.x + threadIdx.x;
    const int N0 = 64 * K0TOT, N1 = 64 * K2TOT, N2 = 4096 * 64;
    if (i < N0) {
        int w = i / K0TOT, k = i - w * K0TOT;
        unsigned d = g_desc0[k >> 3];
        int ty = d >> 12, u = (d >> 6) & 63, v = (d & 63) + (k & 7);
        float val = 0.0f;
        if (ty == 0)      { if (v > u) val = c1  * w1[triq(u, v) * 64 + w]; }
        else if (ty == 1) { val = c2  * w2[v * 64 + w]; }
        else if (ty == 2) { if (v > u) val = c2  * w4[triq(u, v) * 64 + w]; }
        else if (ty == 3) { val = c5s * w5[v * 64 + w]; }
        g_B0t[i] = u2f(rna(val));
    } else if (i < N0 + N1) {
        int j = i - N0;
        int w = j / K2TOT, k = j - w * K2TOT;
        unsigned d = g_desc2[k >> 3];
        int ty = d >> 12, u = (d >> 6) & 63, v = (d & 63) + (k & 7);
        float val = 0.0f;
        if (ty == 0 && v > u) val = c6s * w6[triq(u, v) * 64 + w];
        g_B6t[j] = u2f(rna(val));
    } else if (i < N0 + N1 + N2) {
        int j = i - N0 - N1;
        int n = j >> 6, u = j & 63;                  // n = w*64 + m
        int w = n >> 6, m = n & 63;
        g_B3p[j] = u2f(rna(w3[(size_t)u * 4096 + m * 64 + w]));
    }
}

// ===================== main body (out0 / out2): 32z x 64w CTA, KC=64 chunks ===============
// 256 threads, 8 warps: warpM = wid&1 (16 rows), warpN = wid>>1 (16 cols). Stride 68.
// MODE 0: out0, split-K y=0..1 (37 KC64 chunks), atomicAdd.
// MODE 2: out2, y = cross component, full K (36 KC64 chunks), direct store.
template<int MODE>
__device__ __forceinline__ void main_body(const float* __restrict__ x,
                                          float* __restrict__ out,
                                          float* dsm, int z0, int y) {
    const int AS_OFF = 0;        const int ABUF = 32 * 68;    // 2176
    const int BS_OFF = 4352;     const int BBUF = 64 * 68;    // 4352
    const int S_OFF  = 13056;
    const int VX_OFF = 15232;
    const int VY_OFF = 17408;
    const int VZ_OFF = 19584;
    const int DSC_OFF = 21760;
    unsigned short* dsc = (unsigned short*)(dsm + DSC_OFF);

    const int tid = threadIdx.x, lane = tid & 31, wid = tid >> 5;
    const int warpM = wid & 1, warpN = wid >> 1;     // 2M x 4N
    const int g = lane >> 2, q4 = lane & 3;

    int NCH, kofs, kz = 0;
    if (MODE == 0) { NCH = 37; kofs = y * 2368; }
    else           { NCH = 36; kofs = 0; kz = y; }
    const int gbase = kofs >> 3;
    const int LDB = (MODE == 0) ? K0TOT : K2TOT;
    const float* Bsrc = (MODE == 0) ? g_B0t : g_B6t;
    const int ca = (kz + 1) % 3, cb = (kz + 2) % 3;
    const int NG = (MODE == 0) ? NG0 : NG2;

    // ---- stage x tile SoA (32 rows) + descriptor table ----
    {
        int col = tid;
        int c = col - 64;
        int m = (c >= 0) ? (c / 3) : 0;
        int k3 = c - m * 3;
        int dstoff = -1;
        if (MODE == 0) {
            if (col < 64)       dstoff = S_OFF + col;
            else if (k3 == 0)   dstoff = VX_OFF + m;
            else if (k3 == 1)   dstoff = VY_OFF + m;
            else                dstoff = VZ_OFF + m;
        } else {
            if (col >= 64 && (k3 == ca || k3 == cb))
                dstoff = ((k3 == 0) ? VX_OFF : (k3 == 1) ? VY_OFF : VZ_OFF) + m;
        }
        if (dstoff >= 0) {
            #pragma unroll 4
            for (int j = 0; j < 32; ++j)
                dsm[dstoff + j * 68] = x[(size_t)(z0 + j) * 256 + col];
        }
    }
    for (int i = tid; i < NG; i += 256)
        dsc[i] = (MODE == 0) ? g_desc0[i] : g_desc2[i];

    const int row = tid >> 3, h = tid & 7;           // 32 rows x 8 groups/chunk (KC=64)
    const float* Sp  = dsm + S_OFF  + row * 68;
    const float* pvx = dsm + VX_OFF + row * 68;
    const float* pvy = dsm + VY_OFF + row * 68;
    const float* pvz = dsm + VZ_OFF + row * 68;
    const float* Pca = dsm + ((ca == 0) ? VX_OFF : (ca == 1) ? VY_OFF : VZ_OFF) + row * 68;
    const float* Pcb = dsm + ((cb == 0) ? VX_OFF : (cb == 1) ? VY_OFF : VZ_OFF) + row * 68;
    const int brow = tid >> 2, bc = tid & 3;         // B stage: 64 rows x 16 floats/thread
    const float* bbase = Bsrc + (size_t)brow * LDB + kofs + bc * 16;

    const uint32_t smem0 = smem_u32(dsm);
    const uint32_t aBase = smem0 + ((warpM * 16 + (lane & 15)) * 68 + (lane >> 4) * 4) * 4;
    const uint32_t bBase = smem0 + BS_OFF * 4
                         + ((warpN * 16 + (lane & 7)) * 68 + ((lane >> 3) & 1) * 4) * 4;

    float acc[2][4];
    #pragma unroll
    for (int nt = 0; nt < 2; ++nt)
        #pragma unroll
        for (int j = 0; j < 4; ++j) acc[nt][j] = 0.0f;

    uint32_t fr[8];
    float4 rb[4];

    #define GEN(CC) do {                                                          \
        unsigned d = dsc[gbase + (CC) * 8 + h];                                   \
        int ty = d >> 12, uu = (d >> 6) & 63, v0 = d & 63;                        \
        float f[8];                                                               \
        if (MODE == 0 && ty <= 1) {                                               \
            float4 p  = *(const float4*)(Sp + v0);                                \
            float4 p2 = *(const float4*)(Sp + v0 + 4);                            \
            if (ty == 0) {                                                        \
                float su = Sp[uu];                                                \
                f[0]=su*p.x;  f[1]=su*p.y;  f[2]=su*p.z;  f[3]=su*p.w;            \
                f[4]=su*p2.x; f[5]=su*p2.y; f[6]=su*p2.z; f[7]=su*p2.w;           \
            } else {                                                              \
                f[0]=p.x*p.x;   f[1]=p.y*p.y;   f[2]=p.z*p.z;   f[3]=p.w*p.w;     \
                f[4]=p2.x*p2.x; f[5]=p2.y*p2.y; f[6]=p2.z*p2.z; f[7]=p2.w*p2.w;   \
            }                                                                     \
        } else if (MODE == 0 && ty <= 3) {                                        \
            float4 xa = *(const float4*)(pvx + v0), xb = *(const float4*)(pvx + v0 + 4); \
            float4 ya = *(const float4*)(pvy + v0), yb = *(const float4*)(pvy + v0 + 4); \
            float4 za = *(const float4*)(pvz + v0), zb = *(const float4*)(pvz + v0 + 4); \
            if (ty == 2) {                                                        \
                float ax = pvx[uu], ay = pvy[uu], az = pvz[uu];                   \
                f[0]=ax*xa.x+ay*ya.x+az*za.x; f[1]=ax*xa.y+ay*ya.y+az*za.y;       \
                f[2]=ax*xa.z+ay*ya.z+az*za.z; f[3]=ax*xa.w+ay*ya.w+az*za.w;       \
                f[4]=ax*xb.x+ay*yb.x+az*zb.x; f[5]=ax*xb.y+ay*yb.y+az*zb.y;       \
                f[6]=ax*xb.z+ay*yb.z+az*zb.z; f[7]=ax*xb.w+ay*yb.w+az*zb.w;       \
            } else {                                                              \
                f[0]=xa.x*xa.x+ya.x*ya.x+za.x*za.x; f[1]=xa.y*xa.y+ya.y*ya.y+za.y*za.y; \
                f[2]=xa.z*xa.z+ya.z*ya.z+za.z*za.z; f[3]=xa.w*xa.w+ya.w*ya.w+za.w*za.w; \
                f[4]=xb.x*xb.x+yb.x*yb.x+zb.x*zb.x; f[5]=xb.y*xb.y+yb.y*yb.y+zb.y*zb.y; \
                f[6]=xb.z*xb.z+yb.z*yb.z+zb.z*zb.z; f[7]=xb.w*xb.w+yb.w*yb.w+zb.w*zb.w; \
            }                                                                     \
        } else if (MODE == 2 && ty == 0) {                                        \
            float4 A0 = *(const float4*)(Pca + v0), A1 = *(const float4*)(Pca + v0 + 4); \
            float4 B0 = *(const float4*)(Pcb + v0), B1 = *(const float4*)(Pcb + v0 + 4); \
            float a0 = Pca[uu], a1 = Pcb[uu];                                     \
            f[0]=a0*B0.x-a1*A0.x; f[1]=a0*B0.y-a1*A0.y;                           \
            f[2]=a0*B0.z-a1*A0.z; f[3]=a0*B0.w-a1*A0.w;                           \
            f[4]=a0*B1.x-a1*A1.x; f[5]=a0*B1.y-a1*A1.y;                           \
            f[6]=a0*B1.z-a1*A1.z; f[7]=a0*B1.w-a1*A1.w;                           \
        } else {                                                                  \
            _Pragma("unroll")                                                     \
            for (int i = 0; i < 8; ++i) f[i] = 0.0f;                              \
        }                                                                         \
        _Pragma("unroll")                                                         \
        for (int i = 0; i < 8; ++i) fr[i] = rna(f[i]);                            \
    } while (0)

    #define STORE_A(CC) do {                                                      \
        float* ap = dsm + AS_OFF + ((CC) & 1) * ABUF + row * 68 + h * 8;          \
        *(float4*)(ap)     = make_float4(u2f(fr[0]), u2f(fr[1]), u2f(fr[2]), u2f(fr[3])); \
        *(float4*)(ap + 4) = make_float4(u2f(fr[4]), u2f(fr[5]), u2f(fr[6]), u2f(fr[7])); \
    } while (0)

    #define STORE_B(CC) do {                                                      \
        float* bp = dsm + BS_OFF + ((CC) & 1) * BBUF + brow * 68 + bc * 16;       \
        *(float4*)(bp + 0)  = rb[0];                                              \
        *(float4*)(bp + 4)  = rb[1];                                              \
        *(float4*)(bp + 8)  = rb[2];                                              \
        *(float4*)(bp + 12) = rb[3];                                              \
    } while (0)

    #define LOAD_B(CC) do {                                                       \
        rb[0] = *(const float4*)(bbase + (CC) * 64);                              \
        rb[1] = *(const float4*)(bbase + (CC) * 64 + 4);                          \
        rb[2] = *(const float4*)(bbase + (CC) * 64 + 8);                          \
        rb[3] = *(const float4*)(bbase + (CC) * 64 + 12);                         \
    } while (0)

    __syncthreads();
    LOAD_B(0);
    GEN(0);
    STORE_A(0);
    STORE_B(0);
    __syncthreads();

    for (int c = 0; c < NCH; ++c) {
        bool more = (c + 1 < NCH);
        if (more) {
            LOAD_B(c + 1);
            GEN(c + 1);
            STORE_A(c + 1);
        }
        {
            uint32_t aT = aBase + (c & 1) * (ABUF * 4);
            uint32_t bT = bBase + (c & 1) * (BBUF * 4);
            #pragma unroll
            for (int k8 = 0; k8 < 8; ++k8) {
                uint32_t a[4], b[2][2];
                ldm_x4(a, aT + k8 * 32);
                ldm_x2(b[0], bT + k8 * 32);
                ldm_x2(b[1], bT + 8 * 68 * 4 + k8 * 32);
                mma8(acc[0], a, b[0]);
                mma8(acc[1], a, b[1]);
            }
        }
        if (more) STORE_B(c + 1);
        __syncthreads();
    }

    {
        int za = z0 + warpM * 16 + g;
        int zb = za + 8;
        #pragma unroll
        for (int nt = 0; nt < 2; ++nt) {
            int col = warpN * 16 + nt * 8 + q4 * 2;
            if (MODE == 0) {
                atomicAdd(out + (size_t)za * NOUT + col,     acc[nt][0]);
                atomicAdd(out + (size_t)za * NOUT + col + 1, acc[nt][1]);
                atomicAdd(out + (size_t)zb * NOUT + col,     acc[nt][2]);
                atomicAdd(out + (size_t)zb * NOUT + col + 1, acc[nt][3]);
            } else {
                out[(size_t)za * NOUT + 256 + col * 3 + kz]       = acc[nt][0];
                out[(size_t)za * NOUT + 256 + (col + 1) * 3 + kz] = acc[nt][1];
                out[(size_t)zb * NOUT + 256 + col * 3 + kz]       = acc[nt][2];
                out[(size_t)zb * NOUT + 256 + (col + 1) * 3 + kz] = acc[nt][3];
            }
        }
    }
    #undef GEN
    #undef STORE_A
    #undef STORE_B
    #undef LOAD_B
}

// ===================== out1 body: z-resident 64z, 32 B-tiles, single-buffered B ===========
__device__ __forceinline__ void tgemm_body(const float* __restrict__ x,
                                           float* __restrict__ out,
                                           float* dsm, int z0) {
    const int AS_OFF = 0;                    // [64][72]
    const int VS_OFF = 4608;                 // [64][196]
    const int BS_OFF = 17152;                // [128][72] single buffer
    float* As = dsm + AS_OFF;
    float* Vs = dsm + VS_OFF;
    float* Bs = dsm + BS_OFF;

    const int tid = threadIdx.x, lane = tid & 31, wid = tid >> 5;
    const int warpM = wid & 3, warpN = wid >> 2;    // 4M x 2N
    const int g = lane >> 2, q4 = lane & 3;

    {   // stage A (rna(s)) pair-interleaved
        int r = tid >> 2, seg = tid & 3;
        int hh = seg >> 1, qq = seg & 1;
        const float* srcA = x + (size_t)(z0 + r) * 256 + hh * 32;
        float* dstA = As + r * 72 + hh * 36;
        #pragma unroll
        for (int t = 0; t < 2; ++t) {
            int je = qq * 4 + t * 2;
            float4 v0 = *(const float4*)(srcA + je * 4);
            float4 v1 = *(const float4*)(srcA + je * 4 + 4);
            *(float2*)(dstA + je * 4 + 0) = make_float2(u2f(rna(v0.x)), u2f(rna(v1.x)));
            *(float2*)(dstA + je * 4 + 2) = make_float2(u2f(rna(v0.y)), u2f(rna(v1.y)));
            *(float2*)(dstA + je * 4 + 4) = make_float2(u2f(rna(v0.z)), u2f(rna(v1.z)));
            *(float2*)(dstA + je * 4 + 6) = make_float2(u2f(rna(v0.w)), u2f(rna(v1.w)));
        }
    }
    {   // stage V vectorized
        int r = tid >> 2, vseg = tid & 3;
        const float4* srcV = (const float4*)(x + (size_t)(z0 + r) * 256 + 64);
        float4* dstV = (float4*)(Vs + r * 196);
        #pragma unroll
        for (int t = 0; t < 12; ++t)
            dstV[vseg * 12 + t] = srcV[vseg * 12 + t];
    }

    const int brow = tid >> 1, bhh = tid & 1;
    const float* bsrc0 = g_B3p + (size_t)brow * 64 + bhh * 32;
    float* bdst = Bs + brow * 72 + bhh * 36;

    float4 rg[8];
    #define LOAD_BT(IT) do {                                                      \
        const float* s = bsrc0 + (size_t)(IT) * 128 * 64;                         \
        _Pragma("unroll")                                                         \
        for (int t = 0; t < 8; ++t) rg[t] = *(const float4*)(s + t * 4);          \
    } while (0)
    #define STORE_BT() do {                                                       \
        _Pragma("unroll")                                                         \
        for (int t = 0; t < 4; ++t) {                                             \
            *(float2*)(bdst + t * 8 + 0) = make_float2(rg[2*t].x, rg[2*t+1].x);   \
            *(float2*)(bdst + t * 8 + 2) = make_float2(rg[2*t].y, rg[2*t+1].y);   \
            *(float2*)(bdst + t * 8 + 4) = make_float2(rg[2*t].z, rg[2*t+1].z);   \
            *(float2*)(bdst + t * 8 + 6) = make_float2(rg[2*t].w, rg[2*t+1].w);   \
        }                                                                         \
    } while (0)

    LOAD_BT(0);
    STORE_BT();
    __syncthreads();

    const float sc = 0.015625f;   // 1/64 == C3/sqrt(3)

    for (int it = 0; it < 32; ++it) {
        if (it + 1 < 32) LOAD_BT(it + 1);

        float acc[8][4];
        #pragma unroll
        for (int nt = 0; nt < 8; ++nt)
            #pragma unroll
            for (int j = 0; j < 4; ++j) acc[nt][j] = 0.0f;

        #pragma unroll
        for (int ch = 0; ch < 2; ++ch) {
            #pragma unroll
            for (int k8 = 0; k8 < 4; ++k8) {
                int ko = ch * 36 + k8 * 8 + q4 * 2;
                uint32_t a[4], b[8][2];
                {
                    float2 lo = *(const float2*)(As + (warpM * 16 + g) * 72 + ko);
                    float2 hi = *(const float2*)(As + (warpM * 16 + 8 + g) * 72 + ko);
                    a[0] = __float_as_uint(lo.x); a[1] = __float_as_uint(hi.x);
                    a[2] = __float_as_uint(lo.y); a[3] = __float_as_uint(hi.y);
                }
                #pragma unroll
                for (int nt = 0; nt < 8; ++nt) {
                    float2 bv = *(const float2*)(Bs + (warpN * 64 + nt * 8 + g) * 72 + ko);
                    b[nt][0] = __float_as_uint(bv.x); b[nt][1] = __float_as_uint(bv.y);
                }
                #pragma unroll
                for (int nt = 0; nt < 8; ++nt)
                    mma8(acc[nt], a, b[nt]);
            }
        }

        {
            int ra = warpM * 16 + g;
            int rb = ra + 8;
            float p[2][3] = {{0,0,0},{0,0,0}};
            #pragma unroll
            for (int nt = 0; nt < 8; ++nt) {
                int m0 = nt * 8 + q4 * 2;
                const float* va = Vs + ra * 196 + 3 * m0;
                const float* vb = Vs + rb * 196 + 3 * m0;
                float2 va01 = *(const float2*)(va);
                float2 va23 = *(const float2*)(va + 2);
                float2 va45 = *(const float2*)(va + 4);
                float2 vb01 = *(const float2*)(vb);
                float2 vb23 = *(const float2*)(vb + 2);
                float2 vb45 = *(const float2*)(vb + 4);
                float c0 = acc[nt][0], c1 = acc[nt][1];
                float d0 = acc[nt][2], d1 = acc[nt][3];
                p[0][0] += c0 * va01.x + c1 * va23.y;
                p[0][1] += c0 * va01.y + c1 * va45.x;
                p[0][2] += c0 * va23.x + c1 * va45.y;
                p[1][0] += d0 * vb01.x + d1 * vb23.y;
                p[1][1] += d0 * vb01.y + d1 * vb45.x;
                p[1][2] += d0 * vb23.x + d1 * vb45.y;
            }
            #pragma unroll
            for (int rr = 0; rr < 2; ++rr)
                #pragma unroll
                for (int k = 0; k < 3; ++k) {
                    p[rr][k] += __shfl_xor_sync(0xFFFFFFFF, p[rr][k], 1);
                    p[rr][k] += __shfl_xor_sync(0xFFFFFFFF, p[rr][k], 2);
                }
            if (q4 == 0) {
                int w = it * 2 + warpN;
                float* oa = out + (size_t)(z0 + ra) * NOUT + 64 + w * 3;
                float* ob = out + (size_t)(z0 + rb) * NOUT + 64 + w * 3;
                oa[0] = p[0][0] * sc; oa[1] = p[0][1] * sc; oa[2] = p[0][2] * sc;
                ob[0] = p[1][0] * sc; ob[1] = p[1][1] * sc; ob[2] = p[1][2] * sc;
            }
        }

        __syncthreads();
        if (it + 1 < 32) { STORE_BT(); __syncthreads(); }
    }
    #undef LOAD_BT
    #undef STORE_BT
}

// ===================== fused kernel: one grid for everything =====================
// bx 0..127      : out1   (z-tile bx, 64z)
// bx 128..895    : out2   (z-tile (bx-128)&255 (32z), comp (bx-128)>>8)
// bx 896..1407   : out0   (z-tile (bx-896)&255 (32z), K-split (bx-896)>>8)
__global__ __launch_bounds__(256) void fused_kernel(const float* __restrict__ x,
                                                    float* __restrict__ out) {
    extern __shared__ __align__(16) float dsm[];
    int bx = blockIdx.x;
    if (bx < 128) {
        tgemm_body(x, out, dsm, bx * 64);
    } else if (bx < 896) {
        int idx = bx - 128;
        main_body<2>(x, out, dsm, (idx & 255) * 32, idx >> 8);
    } else {
        int idx = bx - 896;
        main_body<0>(x, out, dsm, (idx & 255) * 32, idx >> 8);
    }
}

// ===================== launch =====================
extern "C" void kernel_launch(void* const* d_in, const int* in_sizes, int n_in,
                              void* d_out, int out_size) {
    const float* x  = (const float*)d_in[0];
    const float* w1 = (const float*)d_in[1];
    const float* w2 = (const float*)d_in[2];
    const float* w3 = (const float*)d_in[3];
    const float* w4 = (const float*)d_in[4];
    const float* w5 = (const float*)d_in[5];
    const float* w6 = (const float*)d_in[6];
    float* out = (float*)d_out;

    float c1  = (float)sqrt(1.0 / 4160.0);     // C1
    float c2  = (float)sqrt(1.0 / 12480.0);    // C2 == C4/sqrt(3)
    float c5s = (float)sqrt(1.0 / 62400.0);    // C5/sqrt(3)
    float c6s = (float)sqrt(1.0 / 4032.0);     // C6/sqrt(6)

    const int FUSED_SMEM = 26368 * 4;          // 105,472 (tgemm branch is largest)
    cudaFuncSetAttribute(fused_kernel, cudaFuncAttributeMaxDynamicSharedMemorySize, FUSED_SMEM);

    cudaMemsetAsync(d_out, 0, (size_t)out_size * sizeof(float));
    init_tables_kernel<<<1, 64>>>();
    const int NTOT = 64 * K0TOT + 64 * K2TOT + 4096 * 64;
    prep_w_kernel<<<(NTOT + 255) / 256, 256>>>(w1, w2, w3, w4, w5, w6, c1, c2, c5s, c6s);

    fused_kernel<<<1408, 256, FUSED_SMEM>>>(x, out);
}

// round 14
// speedup vs baseline: 1.5924x; 1.5924x over previous
#include <cuda_runtime.h>
#include <cstdint>
#include <cmath>

#define ZDIM 8192
#define NOUT 448

#define K0TOT 4736          // out0 padded K (592 groups)
#define K2TOT 2304          // out2 padded K (288 groups)
#define NG0   592
#define NG2   288

// ===================== device globals (no allocation) =====================
static __device__ float g_B0t[64 * K0TOT];         // out0 weights [w][k'], prescaled + tf32
static __device__ float g_B6t[64 * K2TOT];         // out2 weights [w][k'], prescaled + tf32
static __device__ float g_B3p[4096 * 64];          // out1 weights [n=(w*64+m)][u], tf32
static __device__ unsigned short g_desc0[NG0];     // group descriptors: type<<12|u<<6|v0
static __device__ unsigned short g_desc2[NG2];

// ===================== helpers =====================
__device__ __forceinline__ uint32_t rna(float f) {
    uint32_t r; asm("cvt.rna.tf32.f32 %0, %1;" : "=r"(r) : "f"(f)); return r;
}
__device__ __forceinline__ float u2f(uint32_t u) { return __uint_as_float(u); }
__device__ __forceinline__ uint32_t smem_u32(const void* p) {
    uint32_t a;
    asm("{ .reg .u64 t; cvta.to.shared.u64 t, %1; cvt.u32.u64 %0, t; }" : "=r"(a) : "l"(p));
    return a;
}
__device__ __forceinline__ void mma8(float* c, const uint32_t* a, const uint32_t* b) {
    asm volatile("mma.sync.aligned.m16n8k8.row.col.f32.tf32.tf32.f32 "
        "{%0,%1,%2,%3}, {%4,%5,%6,%7}, {%8,%9}, {%0,%1,%2,%3};"
        : "+f"(c[0]), "+f"(c[1]), "+f"(c[2]), "+f"(c[3])
        : "r"(a[0]), "r"(a[1]), "r"(a[2]), "r"(a[3]), "r"(b[0]), "r"(b[1]));
}
__device__ __forceinline__ void ldm_x4(uint32_t* r, uint32_t addr) {
    asm volatile("ldmatrix.sync.aligned.m8n8.x4.shared.b16 {%0,%1,%2,%3}, [%4];"
        : "=r"(r[0]), "=r"(r[1]), "=r"(r[2]), "=r"(r[3]) : "r"(addr));
}
__device__ __forceinline__ void ldm_x2(uint32_t* r, uint32_t addr) {
    asm volatile("ldmatrix.sync.aligned.m8n8.x2.shared.b16 {%0,%1}, [%2];"
        : "=r"(r[0]), "=r"(r[1]) : "r"(addr));
}
__device__ __forceinline__ int triq(int u, int v) {   // triu index, valid v>u
    return u * 63 - (u * (u - 1)) / 2 + (v - u - 1);
}

// ===================== setup kernels =====================
__global__ void init_tables_kernel() {
    int u = threadIdx.x;  // 64 threads
    if (u < 63) {
        int B = u >> 3, r = u & 7;
        int cum = 8 * (8 * B - (B * (B - 1)) / 2) + r * (8 - B);
        int cnt = 8 - B;
        for (int t = 0; t < cnt; ++t) {
            int v0 = 8 * (B + t);
            g_desc0[cum + t]       = (unsigned short)((0 << 12) | (u << 6) | v0);  // ss
            g_desc0[295 + cum + t] = (unsigned short)((2 << 12) | (u << 6) | v0);  // vdot
            g_desc2[cum + t]       = (unsigned short)((0 << 12) | (u << 6) | v0);  // cross
        }
    }
    if (u < 8) {
        g_desc0[287 + u] = (unsigned short)((1 << 12) | (8 * u));   // s^2 octet
        g_desc0[582 + u] = (unsigned short)((3 << 12) | (8 * u));   // |v|^2 octet
    }
    if (u < 2) g_desc0[590 + u] = (unsigned short)(4 << 12);        // pad
    if (u == 0) g_desc2[287] = (unsigned short)(4 << 12);           // pad
}

__global__ void prep_w_kernel(const float* __restrict__ w1, const float* __restrict__ w2,
                              const float* __restrict__ w3, const float* __restrict__ w4,
                              const float* __restrict__ w5, const float* __restrict__ w6,
                              float c1, float c2, float c5s, float c6s) {
    int i = blockIdx.x * blockDim.x + threadIdx.x;
    const int N0 = 64 * K0TOT, N1 = 64 * K2TOT, N2 = 4096 * 64;
    if (i < N0) {
        int w = i / K0TOT, k = i - w * K0TOT;
        unsigned d = g_desc0[k >> 3];
        int ty = d >> 12, u = (d >> 6) & 63, v = (d & 63) + (k & 7);
        float val = 0.0f;
        if (ty == 0)      { if (v > u) val = c1  * w1[triq(u, v) * 64 + w]; }
        else if (ty == 1) { val = c2  * w2[v * 64 + w]; }
        else if (ty == 2) { if (v > u) val = c2  * w4[triq(u, v) * 64 + w]; }
        else if (ty == 3) { val = c5s * w5[v * 64 + w]; }
        g_B0t[i] = u2f(rna(val));
    } else if (i < N0 + N1) {
        int j = i - N0;
        int w = j / K2TOT, k = j - w * K2TOT;
        unsigned d = g_desc2[k >> 3];
        int ty = d >> 12, u = (d >> 6) & 63, v = (d & 63) + (k & 7);
        float val = 0.0f;
        if (ty == 0 && v > u) val = c6s * w6[triq(u, v) * 64 + w];
        g_B6t[j] = u2f(rna(val));
    } else if (i < N0 + N1 + N2) {
        int j = i - N0 - N1;
        int n = j >> 6, u = j & 63;                  // n = w*64 + m
        int w = n >> 6, m = n & 63;
        g_B3p[j] = u2f(rna(w3[(size_t)u * 4096 + m * 64 + w]));
    }
}

// ===================== out0 body: 64z x 64w CTA, KC=32 chunks (R12-proven) ================
__device__ __forceinline__ void out0_body(const float* __restrict__ x,
                                          float* __restrict__ out,
                                          float* dsm, int z0, int y) {
    const int AS_OFF = 0;        const int ABUF = 64 * 44;    // 2816
    const int BS_OFF = 5632;     const int BBUF = 64 * 36;    // 2304
    const int S_OFF  = 10240;
    const int VX_OFF = 14592;
    const int VY_OFF = 18944;
    const int VZ_OFF = 23296;
    const int DSC_OFF = 27648;
    unsigned short* dsc = (unsigned short*)(dsm + DSC_OFF);

    const int tid = threadIdx.x, lane = tid & 31, wid = tid >> 5;
    const int warpM = wid & 1, warpN = wid >> 1;     // 2M x 4N
    const int g = lane >> 2, q4 = lane & 3;

    const int NCH = 37;
    const int kofs = y * 1184;
    const int gbase = kofs >> 3;

    // ---- stage x tile SoA + descriptor table ----
    {
        int col = tid;
        int c = col - 64;
        int m = (c >= 0) ? (c / 3) : 0;
        int k3 = c - m * 3;
        int dstoff;
        if (col < 64)       dstoff = S_OFF + col;
        else if (k3 == 0)   dstoff = VX_OFF + m;
        else if (k3 == 1)   dstoff = VY_OFF + m;
        else                dstoff = VZ_OFF + m;
        #pragma unroll 4
        for (int j = 0; j < 64; ++j)
            dsm[dstoff + j * 68] = x[(size_t)(z0 + j) * 256 + col];
    }
    for (int i = tid; i < NG0; i += 256) dsc[i] = g_desc0[i];

    const int row = tid >> 2, h = tid & 3;           // 64 rows x 4 groups/chunk
    const float* Sp  = dsm + S_OFF  + row * 68;
    const float* pvx = dsm + VX_OFF + row * 68;
    const float* pvy = dsm + VY_OFF + row * 68;
    const float* pvz = dsm + VZ_OFF + row * 68;
    const int brow = tid >> 2, bc = tid & 3;         // B stage: 64 rows, 2 float4 each
    const float* bbase = g_B0t + (size_t)brow * K0TOT + kofs;

    const uint32_t smem0 = smem_u32(dsm);
    const uint32_t aBase = smem0 + ((warpM * 32 + (lane & 15)) * 44 + (lane >> 4) * 4) * 4;
    const uint32_t bBase = smem0 + BS_OFF * 4
                         + ((warpN * 16 + (lane & 7)) * 36 + ((lane >> 3) & 1) * 4) * 4;

    float acc[2][2][4];
    #pragma unroll
    for (int mt = 0; mt < 2; ++mt)
        #pragma unroll
        for (int nt = 0; nt < 2; ++nt)
            #pragma unroll
            for (int j = 0; j < 4; ++j) acc[mt][nt][j] = 0.0f;

    uint32_t fr[8];
    float4 rb0, rb1;

    #define GEN(CC) do {                                                          \
        unsigned d = dsc[gbase + (CC) * 4 + h];                                   \
        int ty = d >> 12, uu = (d >> 6) & 63, v0 = d & 63;                        \
        float f[8];                                                               \
        if (ty <= 1) {                                                            \
            float4 p  = *(const float4*)(Sp + v0);                                \
            float4 p2 = *(const float4*)(Sp + v0 + 4);                            \
            if (ty == 0) {                                                        \
                float su = Sp[uu];                                                \
                f[0]=su*p.x;  f[1]=su*p.y;  f[2]=su*p.z;  f[3]=su*p.w;            \
                f[4]=su*p2.x; f[5]=su*p2.y; f[6]=su*p2.z; f[7]=su*p2.w;           \
            } else {                                                              \
                f[0]=p.x*p.x;   f[1]=p.y*p.y;   f[2]=p.z*p.z;   f[3]=p.w*p.w;     \
                f[4]=p2.x*p2.x; f[5]=p2.y*p2.y; f[6]=p2.z*p2.z; f[7]=p2.w*p2.w;   \
            }                                                                     \
        } else if (ty <= 3) {                                                     \
            float4 xa = *(const float4*)(pvx + v0), xb = *(const float4*)(pvx + v0 + 4); \
            float4 ya = *(const float4*)(pvy + v0), yb = *(const float4*)(pvy + v0 + 4); \
            float4 za = *(const float4*)(pvz + v0), zb = *(const float4*)(pvz + v0 + 4); \
            if (ty == 2) {                                                        \
                float ax = pvx[uu], ay = pvy[uu], az = pvz[uu];                   \
                f[0]=ax*xa.x+ay*ya.x+az*za.x; f[1]=ax*xa.y+ay*ya.y+az*za.y;       \
                f[2]=ax*xa.z+ay*ya.z+az*za.z; f[3]=ax*xa.w+ay*ya.w+az*za.w;       \
                f[4]=ax*xb.x+ay*yb.x+az*zb.x; f[5]=ax*xb.y+ay*yb.y+az*zb.y;       \
                f[6]=ax*xb.z+ay*yb.z+az*zb.z; f[7]=ax*xb.w+ay*yb.w+az*zb.w;       \
            } else {                                                              \
                f[0]=xa.x*xa.x+ya.x*ya.x+za.x*za.x; f[1]=xa.y*xa.y+ya.y*ya.y+za.y*za.y; \
                f[2]=xa.z*xa.z+ya.z*ya.z+za.z*za.z; f[3]=xa.w*xa.w+ya.w*ya.w+za.w*za.w; \
                f[4]=xb.x*xb.x+yb.x*yb.x+zb.x*zb.x; f[5]=xb.y*xb.y+yb.y*yb.y+zb.y*zb.y; \
                f[6]=xb.z*xb.z+yb.z*yb.z+zb.z*zb.z; f[7]=xb.w*xb.w+yb.w*yb.w+zb.w*zb.w; \
            }                                                                     \
        } else {                                                                  \
            _Pragma("unroll")                                                     \
            for (int i = 0; i < 8; ++i) f[i] = 0.0f;                              \
        }                                                                         \
        _Pragma("unroll")                                                         \
        for (int i = 0; i < 8; ++i) fr[i] = rna(f[i]);                            \
    } while (0)

    #define STORE_A(CC) do {                                                      \
        float* ap = dsm + AS_OFF + ((CC) & 1) * ABUF + row * 44 + h * 8;          \
        *(float4*)(ap)     = make_float4(u2f(fr[0]), u2f(fr[1]), u2f(fr[2]), u2f(fr[3])); \
        *(float4*)(ap + 4) = make_float4(u2f(fr[4]), u2f(fr[5]), u2f(fr[6]), u2f(fr[7])); \
    } while (0)

    #define STORE_B(CC) do {                                                      \
        float* bp = dsm + BS_OFF + ((CC) & 1) * BBUF + brow * 36;                 \
        *(float4*)(bp + bc * 4)       = rb0;                                      \
        *(float4*)(bp + (bc + 4) * 4) = rb1;                                      \
    } while (0)

    #define LOAD_B(CC) do {                                                       \
        rb0 = *(const float4*)(bbase + (CC) * 32 + bc * 4);                       \
        rb1 = *(const float4*)(bbase + (CC) * 32 + (bc + 4) * 4);                 \
    } while (0)

    __syncthreads();
    LOAD_B(0);
    GEN(0);
    STORE_A(0);
    STORE_B(0);
    __syncthreads();

    for (int c = 0; c < NCH; ++c) {
        bool more = (c + 1 < NCH);
        if (more) {
            LOAD_B(c + 1);
            GEN(c + 1);
            STORE_A(c + 1);
        }
        {
            uint32_t aT = aBase + (c & 1) * (ABUF * 4);
            uint32_t bT = bBase + (c & 1) * (BBUF * 4);
            #pragma unroll
            for (int k8 = 0; k8 < 4; ++k8) {
                uint32_t a[2][4], b[2][2];
                ldm_x4(a[0], aT + k8 * 32);
                ldm_x4(a[1], aT + 16 * 44 * 4 + k8 * 32);
                ldm_x2(b[0], bT + k8 * 32);
                ldm_x2(b[1], bT + 8 * 36 * 4 + k8 * 32);
                #pragma unroll
                for (int mt = 0; mt < 2; ++mt)
                    #pragma unroll
                    for (int nt = 0; nt < 2; ++nt)
                        mma8(acc[mt][nt], a[mt], b[nt]);
            }
        }
        if (more) STORE_B(c + 1);
        __syncthreads();
    }

    #pragma unroll
    for (int mt = 0; mt < 2; ++mt) {
        int za = z0 + warpM * 32 + mt * 16 + g;
        int zb = za + 8;
        #pragma unroll
        for (int nt = 0; nt < 2; ++nt) {
            int col = warpN * 16 + nt * 8 + q4 * 2;
            atomicAdd(out + (size_t)za * NOUT + col,     acc[mt][nt][0]);
            atomicAdd(out + (size_t)za * NOUT + col + 1, acc[mt][nt][1]);
            atomicAdd(out + (size_t)zb * NOUT + col,     acc[mt][nt][2]);
            atomicAdd(out + (size_t)zb * NOUT + col + 1, acc[mt][nt][3]);
        }
    }
    #undef GEN
    #undef STORE_A
    #undef STORE_B
    #undef LOAD_B
}

// ===================== out2 body: 64z CTA computes ALL 3 cross components ================
// B (w6) shared across components: staged once per chunk. 3 single-buffered A tiles,
// double-buffered B, 2 syncs per chunk. Direct stores, full K (72 chunks).
__device__ __forceinline__ void out2_body(const float* __restrict__ x,
                                          float* __restrict__ out,
                                          float* dsm, int z0) {
    const int A3_OFF = 0;      const int ABUF = 64 * 44;     // 2816 floats per comp
    const int BS_OFF = 8448;   const int BBUF = 64 * 36;     // 2304 floats
    const int VX_OFF = 13056;                                // [64][68]
    const int VY_OFF = 17408;
    const int VZ_OFF = 21760;
    const int DSC_OFF = 26112;
    unsigned short* dsc = (unsigned short*)(dsm + DSC_OFF);

    const int tid = threadIdx.x, lane = tid & 31, wid = tid >> 5;
    const int warpM = wid & 1, warpN = wid >> 1;     // 2M x 4N
    const int g = lane >> 2, q4 = lane & 3;

    // ---- stage v planes ----
    if (tid >= 64) {
        int c = tid - 64;
        int m = c / 3, k3 = c - m * 3;
        int dstoff = ((k3 == 0) ? VX_OFF : (k3 == 1) ? VY_OFF : VZ_OFF) + m;
        #pragma unroll 4
        for (int j = 0; j < 64; ++j)
            dsm[dstoff + j * 68] = x[(size_t)(z0 + j) * 256 + tid];
    }
    for (int i = tid; i < NG2; i += 256) dsc[i] = g_desc2[i];

    const int row = tid >> 2, h = tid & 3;           // 64 rows x 4 groups/chunk
    const float* pvx = dsm + VX_OFF + row * 68;
    const float* pvy = dsm + VY_OFF + row * 68;
    const float* pvz = dsm + VZ_OFF + row * 68;
    const int brow = tid >> 2, bc = tid & 3;
    const float* bbase = g_B6t + (size_t)brow * K2TOT;

    const uint32_t smem0 = smem_u32(dsm);
    const uint32_t aBase = smem0 + ((warpM * 32 + (lane & 15)) * 44 + (lane >> 4) * 4) * 4;
    const uint32_t bBase = smem0 + BS_OFF * 4
                         + ((warpN * 16 + (lane & 7)) * 36 + ((lane >> 3) & 1) * 4) * 4;

    float acc[3][2][2][4];
    #pragma unroll
    for (int cp = 0; cp < 3; ++cp)
        #pragma unroll
        for (int mt = 0; mt < 2; ++mt)
            #pragma unroll
            for (int nt = 0; nt < 2; ++nt)
                #pragma unroll
                for (int j = 0; j < 4; ++j) acc[cp][mt][nt][j] = 0.0f;

    uint32_t fr[3][8];
    float4 rb0, rb1;

    #define GEN2(CC) do {                                                         \
        unsigned d = dsc[(CC) * 4 + h];                                           \
        int ty = d >> 12, uu = (d >> 6) & 63, v0 = d & 63;                        \
        if (ty == 0) {                                                            \
            float4 X0 = *(const float4*)(pvx + v0), X1 = *(const float4*)(pvx + v0 + 4); \
            float4 Y0 = *(const float4*)(pvy + v0), Y1 = *(const float4*)(pvy + v0 + 4); \
            float4 Z0 = *(const float4*)(pvz + v0), Z1 = *(const float4*)(pvz + v0 + 4); \
            float ax = pvx[uu], ay = pvy[uu], az = pvz[uu];                       \
            float Xv[8] = {X0.x,X0.y,X0.z,X0.w,X1.x,X1.y,X1.z,X1.w};              \
            float Yv[8] = {Y0.x,Y0.y,Y0.z,Y0.w,Y1.x,Y1.y,Y1.z,Y1.w};              \
            float Zv[8] = {Z0.x,Z0.y,Z0.z,Z0.w,Z1.x,Z1.y,Z1.z,Z1.w};              \
            _Pragma("unroll")                                                     \
            for (int i = 0; i < 8; ++i) {                                         \
                fr[0][i] = rna(ay * Zv[i] - az * Yv[i]);                          \
                fr[1][i] = rna(az * Xv[i] - ax * Zv[i]);                          \
                fr[2][i] = rna(ax * Yv[i] - ay * Xv[i]);                          \
            }                                                                     \
        } else {                                                                  \
            _Pragma("unroll")                                                     \
            for (int i = 0; i < 8; ++i) {                                         \
                fr[0][i] = 0u; fr[1][i] = 0u; fr[2][i] = 0u;                      \
            }                                                                     \
        }                                                                         \
    } while (0)

    #define STORE_A3() do {                                                       \
        _Pragma("unroll")                                                         \
        for (int cp = 0; cp < 3; ++cp) {                                          \
            float* ap = dsm + A3_OFF + cp * ABUF + row * 44 + h * 8;              \
            *(float4*)(ap)     = make_float4(u2f(fr[cp][0]), u2f(fr[cp][1]), u2f(fr[cp][2]), u2f(fr[cp][3])); \
            *(float4*)(ap + 4) = make_float4(u2f(fr[cp][4]), u2f(fr[cp][5]), u2f(fr[cp][6]), u2f(fr[cp][7])); \
        }                                                                         \
    } while (0)

    #define STORE_B2(CC) do {                                                     \
        float* bp = dsm + BS_OFF + ((CC) & 1) * BBUF + brow * 36;                 \
        *(float4*)(bp + bc * 4)       = rb0;                                      \
        *(float4*)(bp + (bc + 4) * 4) = rb1;                                      \
    } while (0)

    #define LOAD_B2(CC) do {                                                      \
        rb0 = *(const float4*)(bbase + (CC) * 32 + bc * 4);                       \
        rb1 = *(const float4*)(bbase + (CC) * 32 + (bc + 4) * 4);                 \
    } while (0)

    __syncthreads();
    LOAD_B2(0);
    GEN2(0);
    STORE_A3();
    STORE_B2(0);
    __syncthreads();

    for (int c = 0; c < 72; ++c) {
        bool more = (c + 1 < 72);
        if (more) {
            LOAD_B2(c + 1);
            GEN2(c + 1);          // into registers only (A is single-buffered)
        }
        {
            uint32_t bT = bBase + (c & 1) * (BBUF * 4);
            #pragma unroll
            for (int k8 = 0; k8 < 4; ++k8) {
                uint32_t b[2][2];
                ldm_x2(b[0], bT + k8 * 32);
                ldm_x2(b[1], bT + 8 * 36 * 4 + k8 * 32);
                #pragma unroll
                for (int cp = 0; cp < 3; ++cp) {
                    uint32_t a[2][4];
                    uint32_t aT = aBase + cp * (ABUF * 4);
                    ldm_x4(a[0], aT + k8 * 32);
                    ldm_x4(a[1], aT + 16 * 44 * 4 + k8 * 32);
                    #pragma unroll
                    for (int mt = 0; mt < 2; ++mt)
                        #pragma unroll
                        for (int nt = 0; nt < 2; ++nt)
                            mma8(acc[cp][mt][nt], a[mt], b[nt]);
                }
            }
        }
        __syncthreads();          // all warps done reading A/B of chunk c
        if (more) {
            STORE_A3();
            STORE_B2(c + 1);
            __syncthreads();      // buffers ready for chunk c+1
        }
    }

    #pragma unroll
    for (int cp = 0; cp < 3; ++cp)
        #pragma unroll
        for (int mt = 0; mt < 2; ++mt) {
            int za = z0 + warpM * 32 + mt * 16 + g;
            int zb = za + 8;
            #pragma unroll
            for (int nt = 0; nt < 2; ++nt) {
                int col = warpN * 16 + nt * 8 + q4 * 2;
                out[(size_t)za * NOUT + 256 + col * 3 + cp]       = acc[cp][mt][nt][0];
                out[(size_t)za * NOUT + 256 + (col + 1) * 3 + cp] = acc[cp][mt][nt][1];
                out[(size_t)zb * NOUT + 256 + col * 3 + cp]       = acc[cp][mt][nt][2];
                out[(size_t)zb * NOUT + 256 + (col + 1) * 3 + cp] = acc[cp][mt][nt][3];
            }
        }
    #undef GEN2
    #undef STORE_A3
    #undef STORE_B2
    #undef LOAD_B2
}

// ===================== out1 body: z-resident, 32 B-tiles, single-buffered B ===============
__device__ __forceinline__ void tgemm_body(const float* __restrict__ x,
                                           float* __restrict__ out,
                                           float* dsm, int z0) {
    const int AS_OFF = 0;                    // [64][72]
    const int VS_OFF = 4608;                 // [64][196]
    const int BS_OFF = 17152;                // [128][72] single buffer
    float* As = dsm + AS_OFF;
    float* Vs = dsm + VS_OFF;
    float* Bs = dsm + BS_OFF;

    const int tid = threadIdx.x, lane = tid & 31, wid = tid >> 5;
    const int warpM = wid & 3, warpN = wid >> 2;    // 4M x 2N
    const int g = lane >> 2, q4 = lane & 3;

    {   // stage A (rna(s)) pair-interleaved
        int r = tid >> 2, seg = tid & 3;
        int hh = seg >> 1, qq = seg & 1;
        const float* srcA = x + (size_t)(z0 + r) * 256 + hh * 32;
        float* dstA = As + r * 72 + hh * 36;
        #pragma unroll
        for (int t = 0; t < 2; ++t) {
            int je = qq * 4 + t * 2;
            float4 v0 = *(const float4*)(srcA + je * 4);
            float4 v1 = *(const float4*)(srcA + je * 4 + 4);
            *(float2*)(dstA + je * 4 + 0) = make_float2(u2f(rna(v0.x)), u2f(rna(v1.x)));
            *(float2*)(dstA + je * 4 + 2) = make_float2(u2f(rna(v0.y)), u2f(rna(v1.y)));
            *(float2*)(dstA + je * 4 + 4) = make_float2(u2f(rna(v0.z)), u2f(rna(v1.z)));
            *(float2*)(dstA + je * 4 + 6) = make_float2(u2f(rna(v0.w)), u2f(rna(v1.w)));
        }
    }
    {   // stage V vectorized
        int r = tid >> 2, vseg = tid & 3;
        const float4* srcV = (const float4*)(x + (size_t)(z0 + r) * 256 + 64);
        float4* dstV = (float4*)(Vs + r * 196);
        #pragma unroll
        for (int t = 0; t < 12; ++t)
            dstV[vseg * 12 + t] = srcV[vseg * 12 + t];
    }

    const int brow = tid >> 1, bhh = tid & 1;
    const float* bsrc0 = g_B3p + (size_t)brow * 64 + bhh * 32;
    float* bdst = Bs + brow * 72 + bhh * 36;

    float4 rg[8];
    #define LOAD_BT(IT) do {                                                      \
        const float* s = bsrc0 + (size_t)(IT) * 128 * 64;                         \
        _Pragma("unroll")                                                         \
        for (int t = 0; t < 8; ++t) rg[t] = *(const float4*)(s + t * 4);          \
    } while (0)
    #define STORE_BT() do {                                                       \
        _Pragma("unroll")                                                         \
        for (int t = 0; t < 4; ++t) {                                             \
            *(float2*)(bdst + t * 8 + 0) = make_float2(rg[2*t].x, rg[2*t+1].x);   \
            *(float2*)(bdst + t * 8 + 2) = make_float2(rg[2*t].y, rg[2*t+1].y);   \
            *(float2*)(bdst + t * 8 + 4) = make_float2(rg[2*t].z, rg[2*t+1].z);   \
            *(float2*)(bdst + t * 8 + 6) = make_float2(rg[2*t].w, rg[2*t+1].w);   \
        }                                                                         \
    } while (0)

    LOAD_BT(0);
    STORE_BT();
    __syncthreads();

    const float sc = 0.015625f;   // 1/64 == C3/sqrt(3)

    for (int it = 0; it < 32; ++it) {
        if (it + 1 < 32) LOAD_BT(it + 1);

        float acc[8][4];
        #pragma unroll
        for (int nt = 0; nt < 8; ++nt)
            #pragma unroll
            for (int j = 0; j < 4; ++j) acc[nt][j] = 0.0f;

        #pragma unroll
        for (int ch = 0; ch < 2; ++ch) {
            #pragma unroll
            for (int k8 = 0; k8 < 4; ++k8) {
                int ko = ch * 36 + k8 * 8 + q4 * 2;
                uint32_t a[4], b[8][2];
                {
                    float2 lo = *(const float2*)(As + (warpM * 16 + g) * 72 + ko);
                    float2 hi = *(const float2*)(As + (warpM * 16 + 8 + g) * 72 + ko);
                    a[0] = __float_as_uint(lo.x); a[1] = __float_as_uint(hi.x);
                    a[2] = __float_as_uint(lo.y); a[3] = __float_as_uint(hi.y);
                }
                #pragma unroll
                for (int nt = 0; nt < 8; ++nt) {
                    float2 bv = *(const float2*)(Bs + (warpN * 64 + nt * 8 + g) * 72 + ko);
                    b[nt][0] = __float_as_uint(bv.x); b[nt][1] = __float_as_uint(bv.y);
                }
                #pragma unroll
                for (int nt = 0; nt < 8; ++nt)
                    mma8(acc[nt], a, b[nt]);
            }
        }

        {
            int ra = warpM * 16 + g;
            int rb = ra + 8;
            float p[2][3] = {{0,0,0},{0,0,0}};
            #pragma unroll
            for (int nt = 0; nt < 8; ++nt) {
                int m0 = nt * 8 + q4 * 2;
                const float* va = Vs + ra * 196 + 3 * m0;
                const float* vb = Vs + rb * 196 + 3 * m0;
                float2 va01 = *(const float2*)(va);
                float2 va23 = *(const float2*)(va + 2);
                float2 va45 = *(const float2*)(va + 4);
                float2 vb01 = *(const float2*)(vb);
                float2 vb23 = *(const float2*)(vb + 2);
                float2 vb45 = *(const float2*)(vb + 4);
                float c0 = acc[nt][0], c1 = acc[nt][1];
                float d0 = acc[nt][2], d1 = acc[nt][3];
                p[0][0] += c0 * va01.x + c1 * va23.y;
                p[0][1] += c0 * va01.y + c1 * va45.x;
                p[0][2] += c0 * va23.x + c1 * va45.y;
                p[1][0] += d0 * vb01.x + d1 * vb23.y;
                p[1][1] += d0 * vb01.y + d1 * vb45.x;
                p[1][2] += d0 * vb23.x + d1 * vb45.y;
            }
            #pragma unroll
            for (int rr = 0; rr < 2; ++rr)
                #pragma unroll
                for (int k = 0; k < 3; ++k) {
                    p[rr][k] += __shfl_xor_sync(0xFFFFFFFF, p[rr][k], 1);
                    p[rr][k] += __shfl_xor_sync(0xFFFFFFFF, p[rr][k], 2);
                }
            if (q4 == 0) {
                int w = it * 2 + warpN;
                float* oa = out + (size_t)(z0 + ra) * NOUT + 64 + w * 3;
                float* ob = out + (size_t)(z0 + rb) * NOUT + 64 + w * 3;
                oa[0] = p[0][0] * sc; oa[1] = p[0][1] * sc; oa[2] = p[0][2] * sc;
                ob[0] = p[1][0] * sc; ob[1] = p[1][1] * sc; ob[2] = p[1][2] * sc;
            }
        }

        __syncthreads();
        if (it + 1 < 32) { STORE_BT(); __syncthreads(); }
    }
    #undef LOAD_BT
    #undef STORE_BT
}

// ===================== fused kernel: one grid for everything =====================
// bx 0..127   : out1 (z-tile bx, 64z)
// bx 128..255 : out2 (z-tile bx-128, 64z, ALL 3 components)
// bx 256..767 : out0 (z-tile (bx-256)&127, K-split (bx-256)>>7)
__global__ __launch_bounds__(256) void fused_kernel(const float* __restrict__ x,
                                                    float* __restrict__ out) {
    extern __shared__ __align__(16) float dsm[];
    int bx = blockIdx.x;
    if (bx < 128) {
        tgemm_body(x, out, dsm, bx * 64);
    } else if (bx < 256) {
        out2_body(x, out, dsm, (bx - 128) * 64);
    } else {
        int idx = bx - 256;
        out0_body(x, out, dsm, (idx & 127) * 64, idx >> 7);
    }
}

// ===================== launch =====================
extern "C" void kernel_launch(void* const* d_in, const int* in_sizes, int n_in,
                              void* d_out, int out_size) {
    const float* x  = (const float*)d_in[0];
    const float* w1 = (const float*)d_in[1];
    const float* w2 = (const float*)d_in[2];
    const float* w3 = (const float*)d_in[3];
    const float* w4 = (const float*)d_in[4];
    const float* w5 = (const float*)d_in[5];
    const float* w6 = (const float*)d_in[6];
    float* out = (float*)d_out;

    float c1  = (float)sqrt(1.0 / 4160.0);     // C1
    float c2  = (float)sqrt(1.0 / 12480.0);    // C2 == C4/sqrt(3)
    float c5s = (float)sqrt(1.0 / 62400.0);    // C5/sqrt(3)
    float c6s = (float)sqrt(1.0 / 4032.0);     // C6/sqrt(6)

    const int FUSED_SMEM = 27648 * 4 + NG0 * 2;   // 111,776 (out0 branch is largest)
    cudaFuncSetAttribute(fused_kernel, cudaFuncAttributeMaxDynamicSharedMemorySize, FUSED_SMEM);

    cudaMemsetAsync(d_out, 0, (size_t)out_size * sizeof(float));
    init_tables_kernel<<<1, 64>>>();
    const int NTOT = 64 * K0TOT + 64 * K2TOT + 4096 * 64;
    prep_w_kernel<<<(NTOT + 255) / 256, 256>>>(w1, w2, w3, w4, w5, w6, c1, c2, c5s, c6s);

    fused_kernel<<<768, 256, FUSED_SMEM>>>(x, out);
}

// round 15
// speedup vs baseline: 1.6755x; 1.0522x over previous
#include <cuda_runtime.h>
#include <cstdint>
#include <cmath>

#define ZDIM 8192
#define NOUT 448

#define K0TOT 4736          // out0 padded K (592 groups)
#define K2TOT 2304          // out2 padded K (288 groups)
#define NG0   592
#define NG2   288

// ===================== compile-time descriptor tables =====================
struct DescTables {
    unsigned short d0[NG0];
    unsigned short d2[NG2];
};
constexpr DescTables make_tables() {
    DescTables t{};
    for (int u = 0; u < 63; ++u) {
        int B = u >> 3, r = u & 7;
        int cum = 8 * (8 * B - (B * (B - 1)) / 2) + r * (8 - B);
        int cnt = 8 - B;
        for (int k = 0; k < cnt; ++k) {
            int v0 = 8 * (B + k);
            t.d0[cum + k]       = (unsigned short)((0 << 12) | (u << 6) | v0);  // ss
            t.d0[295 + cum + k] = (unsigned short)((2 << 12) | (u << 6) | v0);  // vdot
            t.d2[cum + k]       = (unsigned short)((0 << 12) | (u << 6) | v0);  // cross
        }
    }
    for (int u = 0; u < 8; ++u) {
        t.d0[287 + u] = (unsigned short)((1 << 12) | (8 * u));   // s^2 octet
        t.d0[582 + u] = (unsigned short)((3 << 12) | (8 * u));   // |v|^2 octet
    }
    t.d0[590] = (unsigned short)(4 << 12);
    t.d0[591] = (unsigned short)(4 << 12);
    t.d2[287] = (unsigned short)(4 << 12);
    return t;
}
static __device__ constexpr DescTables g_tables = make_tables();

// ===================== device globals (no allocation) =====================
static __device__ float g_B0t[64 * K0TOT];         // out0 weights [w][k'], prescaled + tf32
static __device__ float g_B6t[64 * K2TOT];         // out2 weights [w][k'], prescaled + tf32
static __device__ float g_B3p[4096 * 64];          // out1 weights [n=(w*64+m)][u], tf32
static __device__ unsigned short g_desc0[NG0];     // gmem copies for fast smem staging
static __device__ unsigned short g_desc2[NG2];

// ===================== helpers =====================
__device__ __forceinline__ uint32_t rna(float f) {
    uint32_t r; asm("cvt.rna.tf32.f32 %0, %1;" : "=r"(r) : "f"(f)); return r;
}
__device__ __forceinline__ float u2f(uint32_t u) { return __uint_as_float(u); }
__device__ __forceinline__ uint32_t smem_u32(const void* p) {
    uint32_t a;
    asm("{ .reg .u64 t; cvta.to.shared.u64 t, %1; cvt.u32.u64 %0, t; }" : "=r"(a) : "l"(p));
    return a;
}
__device__ __forceinline__ void mma8(float* c, const uint32_t* a, const uint32_t* b) {
    asm volatile("mma.sync.aligned.m16n8k8.row.col.f32.tf32.tf32.f32 "
        "{%0,%1,%2,%3}, {%4,%5,%6,%7}, {%8,%9}, {%0,%1,%2,%3};"
        : "+f"(c[0]), "+f"(c[1]), "+f"(c[2]), "+f"(c[3])
        : "r"(a[0]), "r"(a[1]), "r"(a[2]), "r"(a[3]), "r"(b[0]), "r"(b[1]));
}
__device__ __forceinline__ void ldm_x4(uint32_t* r, uint32_t addr) {
    asm volatile("ldmatrix.sync.aligned.m8n8.x4.shared.b16 {%0,%1,%2,%3}, [%4];"
        : "=r"(r[0]), "=r"(r[1]), "=r"(r[2]), "=r"(r[3]) : "r"(addr));
}
__device__ __forceinline__ void ldm_x2(uint32_t* r, uint32_t addr) {
    asm volatile("ldmatrix.sync.aligned.m8n8.x2.shared.b16 {%0,%1}, [%2];"
        : "=r"(r[0]), "=r"(r[1]) : "r"(addr));
}
__device__ __forceinline__ int triq(int u, int v) {   // triu index, valid v>u
    return u * 63 - (u * (u - 1)) / 2 + (v - u - 1);
}

// ===================== setup kernel (weights + table copies) =====================
__global__ void prep_w_kernel(const float* __restrict__ w1, const float* __restrict__ w2,
                              const float* __restrict__ w3, const float* __restrict__ w4,
                              const float* __restrict__ w5, const float* __restrict__ w6,
                              float c1, float c2, float c5s, float c6s) {
    int i = blockIdx.x * blockDim.x + threadIdx.x;
    if (i < NG0) g_desc0[i] = g_tables.d0[i];
    if (i < NG2) g_desc2[i] = g_tables.d2[i];
    const int N0 = 64 * K0TOT, N1 = 64 * K2TOT, N2 = 4096 * 64;
    if (i < N0) {
        int w = i / K0TOT, k = i - w * K0TOT;
        unsigned d = g_tables.d0[k >> 3];
        int ty = d >> 12, u = (d >> 6) & 63, v = (d & 63) + (k & 7);
        float val = 0.0f;
        if (ty == 0)      { if (v > u) val = c1  * w1[triq(u, v) * 64 + w]; }
        else if (ty == 1) { val = c2  * w2[v * 64 + w]; }
        else if (ty == 2) { if (v > u) val = c2  * w4[triq(u, v) * 64 + w]; }
        else if (ty == 3) { val = c5s * w5[v * 64 + w]; }
        g_B0t[i] = u2f(rna(val));
    } else if (i < N0 + N1) {
        int j = i - N0;
        int w = j / K2TOT, k = j - w * K2TOT;
        unsigned d = g_tables.d2[k >> 3];
        int ty = d >> 12, u = (d >> 6) & 63, v = (d & 63) + (k & 7);
        float val = 0.0f;
        if (ty == 0 && v > u) val = c6s * w6[triq(u, v) * 64 + w];
        g_B6t[j] = u2f(rna(val));
    } else if (i < N0 + N1 + N2) {
        int j = i - N0 - N1;
        int n = j >> 6, u = j & 63;                  // n = w*64 + m
        int w = n >> 6, m = n & 63;
        g_B3p[j] = u2f(rna(w3[(size_t)u * 4096 + m * 64 + w]));
    }
}

// ===================== out0 body: 64z x 64w CTA, KC=32 chunks, split-K 2 ==================
__device__ __forceinline__ void out0_body(const float* __restrict__ x,
                                          float* __restrict__ out,
                                          float* dsm, int z0, int y) {
    const int AS_OFF = 0;        const int ABUF = 64 * 44;    // 2816
    const int BS_OFF = 5632;     const int BBUF = 64 * 36;    // 2304
    const int S_OFF  = 10240;
    const int VX_OFF = 14592;
    const int VY_OFF = 18944;
    const int VZ_OFF = 23296;
    const int DSC_OFF = 27648;
    unsigned short* dsc = (unsigned short*)(dsm + DSC_OFF);

    const int tid = threadIdx.x, lane = tid & 31, wid = tid >> 5;
    const int warpM = wid & 1, warpN = wid >> 1;     // 2M x 4N
    const int g = lane >> 2, q4 = lane & 3;

    const int NCH = 74;
    const int kofs = y * 2368;
    const int gbase = kofs >> 3;

    // ---- stage x tile SoA + descriptor table ----
    {
        int col = tid;
        int c = col - 64;
        int m = (c >= 0) ? (c / 3) : 0;
        int k3 = c - m * 3;
        int dstoff;
        if (col < 64)       dstoff = S_OFF + col;
        else if (k3 == 0)   dstoff = VX_OFF + m;
        else if (k3 == 1)   dstoff = VY_OFF + m;
        else                dstoff = VZ_OFF + m;
        #pragma unroll 4
        for (int j = 0; j < 64; ++j)
            dsm[dstoff + j * 68] = x[(size_t)(z0 + j) * 256 + col];
    }
    for (int i = tid; i < NG0; i += 256) dsc[i] = g_desc0[i];

    const int row = tid >> 2, h = tid & 3;           // 64 rows x 4 groups/chunk
    const float* Sp  = dsm + S_OFF  + row * 68;
    const float* pvx = dsm + VX_OFF + row * 68;
    const float* pvy = dsm + VY_OFF + row * 68;
    const float* pvz = dsm + VZ_OFF + row * 68;
    const int brow = tid >> 2, bc = tid & 3;         // B stage: 64 rows, 2 float4 each
    const float* bbase = g_B0t + (size_t)brow * K0TOT + kofs;

    const uint32_t smem0 = smem_u32(dsm);
    const uint32_t aBase = smem0 + ((warpM * 32 + (lane & 15)) * 44 + (lane >> 4) * 4) * 4;
    const uint32_t bBase = smem0 + BS_OFF * 4
                         + ((warpN * 16 + (lane & 7)) * 36 + ((lane >> 3) & 1) * 4) * 4;

    float acc[2][2][4];
    #pragma unroll
    for (int mt = 0; mt < 2; ++mt)
        #pragma unroll
        for (int nt = 0; nt < 2; ++nt)
            #pragma unroll
            for (int j = 0; j < 4; ++j) acc[mt][nt][j] = 0.0f;

    uint32_t fr[8];
    float4 rb0, rb1;

    #define GEN(CC) do {                                                          \
        unsigned d = dsc[gbase + (CC) * 4 + h];                                   \
        int ty = d >> 12, uu = (d >> 6) & 63, v0 = d & 63;                        \
        float f[8];                                                               \
        if (ty <= 1) {                                                            \
            float4 p  = *(const float4*)(Sp + v0);                                \
            float4 p2 = *(const float4*)(Sp + v0 + 4);                            \
            if (ty == 0) {                                                        \
                float su = Sp[uu];                                                \
                f[0]=su*p.x;  f[1]=su*p.y;  f[2]=su*p.z;  f[3]=su*p.w;            \
                f[4]=su*p2.x; f[5]=su*p2.y; f[6]=su*p2.z; f[7]=su*p2.w;           \
            } else {                                                              \
                f[0]=p.x*p.x;   f[1]=p.y*p.y;   f[2]=p.z*p.z;   f[3]=p.w*p.w;     \
                f[4]=p2.x*p2.x; f[5]=p2.y*p2.y; f[6]=p2.z*p2.z; f[7]=p2.w*p2.w;   \
            }                                                                     \
        } else if (ty <= 3) {                                                     \
            float4 xa = *(const float4*)(pvx + v0), xb = *(const float4*)(pvx + v0 + 4); \
            float4 ya = *(const float4*)(pvy + v0), yb = *(const float4*)(pvy + v0 + 4); \
            float4 za = *(const float4*)(pvz + v0), zb = *(const float4*)(pvz + v0 + 4); \
            if (ty == 2) {                                                        \
                float ax = pvx[uu], ay = pvy[uu], az = pvz[uu];                   \
                f[0]=ax*xa.x+ay*ya.x+az*za.x; f[1]=ax*xa.y+ay*ya.y+az*za.y;       \
                f[2]=ax*xa.z+ay*ya.z+az*za.z; f[3]=ax*xa.w+ay*ya.w+az*za.w;       \
                f[4]=ax*xb.x+ay*yb.x+az*zb.x; f[5]=ax*xb.y+ay*yb.y+az*zb.y;       \
                f[6]=ax*xb.z+ay*yb.z+az*zb.z; f[7]=ax*xb.w+ay*yb.w+az*zb.w;       \
            } else {                                                              \
                f[0]=xa.x*xa.x+ya.x*ya.x+za.x*za.x; f[1]=xa.y*xa.y+ya.y*ya.y+za.y*za.y; \
                f[2]=xa.z*xa.z+ya.z*ya.z+za.z*za.z; f[3]=xa.w*xa.w+ya.w*ya.w+za.w*za.w; \
                f[4]=xb.x*xb.x+yb.x*yb.x+zb.x*zb.x; f[5]=xb.y*xb.y+yb.y*yb.y+zb.y*zb.y; \
                f[6]=xb.z*xb.z+yb.z*yb.z+zb.z*zb.z; f[7]=xb.w*xb.w+yb.w*yb.w+zb.w*zb.w; \
            }                                                                     \
        } else {                                                                  \
            _Pragma("unroll")                                                     \
            for (int i = 0; i < 8; ++i) f[i] = 0.0f;                              \
        }                                                                         \
        _Pragma("unroll")                                                         \
        for (int i = 0; i < 8; ++i) fr[i] = rna(f[i]);                            \
    } while (0)

    #define STORE_A(CC) do {                                                      \
        float* ap = dsm + AS_OFF + ((CC) & 1) * ABUF + row * 44 + h * 8;          \
        *(float4*)(ap)     = make_float4(u2f(fr[0]), u2f(fr[1]), u2f(fr[2]), u2f(fr[3])); \
        *(float4*)(ap + 4) = make_float4(u2f(fr[4]), u2f(fr[5]), u2f(fr[6]), u2f(fr[7])); \
    } while (0)

    #define STORE_B(CC) do {                                                      \
        float* bp = dsm + BS_OFF + ((CC) & 1) * BBUF + brow * 36;                 \
        *(float4*)(bp + bc * 4)       = rb0;                                      \
        *(float4*)(bp + (bc + 4) * 4) = rb1;                                      \
    } while (0)

    #define LOAD_B(CC) do {                                                       \
        rb0 = *(const float4*)(bbase + (CC) * 32 + bc * 4);                       \
        rb1 = *(const float4*)(bbase + (CC) * 32 + (bc + 4) * 4);                 \
    } while (0)

    __syncthreads();
    LOAD_B(0);
    GEN(0);
    STORE_A(0);
    STORE_B(0);
    __syncthreads();

    for (int c = 0; c < NCH; ++c) {
        bool more = (c + 1 < NCH);
        if (more) {
            LOAD_B(c + 1);
            GEN(c + 1);
            STORE_A(c + 1);
        }
        {
            uint32_t aT = aBase + (c & 1) * (ABUF * 4);
            uint32_t bT = bBase + (c & 1) * (BBUF * 4);
            #pragma unroll
            for (int k8 = 0; k8 < 4; ++k8) {
                uint32_t a[2][4], b[2][2];
                ldm_x4(a[0], aT + k8 * 32);
                ldm_x4(a[1], aT + 16 * 44 * 4 + k8 * 32);
                ldm_x2(b[0], bT + k8 * 32);
                ldm_x2(b[1], bT + 8 * 36 * 4 + k8 * 32);
                #pragma unroll
                for (int mt = 0; mt < 2; ++mt)
                    #pragma unroll
                    for (int nt = 0; nt < 2; ++nt)
                        mma8(acc[mt][nt], a[mt], b[nt]);
            }
        }
        if (more) STORE_B(c + 1);
        __syncthreads();
    }

    #pragma unroll
    for (int mt = 0; mt < 2; ++mt) {
        int za = z0 + warpM * 32 + mt * 16 + g;
        int zb = za + 8;
        #pragma unroll
        for (int nt = 0; nt < 2; ++nt) {
            int col = warpN * 16 + nt * 8 + q4 * 2;
            atomicAdd(out + (size_t)za * NOUT + col,     acc[mt][nt][0]);
            atomicAdd(out + (size_t)za * NOUT + col + 1, acc[mt][nt][1]);
            atomicAdd(out + (size_t)zb * NOUT + col,     acc[mt][nt][2]);
            atomicAdd(out + (size_t)zb * NOUT + col + 1, acc[mt][nt][3]);
        }
    }
    #undef GEN
    #undef STORE_A
    #undef STORE_B
    #undef LOAD_B
}

// ===================== out2 body: 64z CTA computes ALL 3 cross components ================
__device__ __forceinline__ void out2_body(const float* __restrict__ x,
                                          float* __restrict__ out,
                                          float* dsm, int z0) {
    const int A3_OFF = 0;      const int ABUF = 64 * 44;     // 2816 floats per comp
    const int BS_OFF = 8448;   const int BBUF = 64 * 36;     // 2304 floats
    const int VX_OFF = 13056;                                // [64][68]
    const int VY_OFF = 17408;
    const int VZ_OFF = 21760;
    const int DSC_OFF = 26112;
    unsigned short* dsc = (unsigned short*)(dsm + DSC_OFF);

    const int tid = threadIdx.x, lane = tid & 31, wid = tid >> 5;
    const int warpM = wid & 1, warpN = wid >> 1;     // 2M x 4N
    const int g = lane >> 2, q4 = lane & 3;

    // ---- stage v planes ----
    if (tid >= 64) {
        int c = tid - 64;
        int m = c / 3, k3 = c - m * 3;
        int dstoff = ((k3 == 0) ? VX_OFF : (k3 == 1) ? VY_OFF : VZ_OFF) + m;
        #pragma unroll 4
        for (int j = 0; j < 64; ++j)
            dsm[dstoff + j * 68] = x[(size_t)(z0 + j) * 256 + tid];
    }
    for (int i = tid; i < NG2; i += 256) dsc[i] = g_desc2[i];

    const int row = tid >> 2, h = tid & 3;           // 64 rows x 4 groups/chunk
    const float* pvx = dsm + VX_OFF + row * 68;
    const float* pvy = dsm + VY_OFF + row * 68;
    const float* pvz = dsm + VZ_OFF + row * 68;
    const int brow = tid >> 2, bc = tid & 3;
    const float* bbase = g_B6t + (size_t)brow * K2TOT;

    const uint32_t smem0 = smem_u32(dsm);
    const uint32_t aBase = smem0 + ((warpM * 32 + (lane & 15)) * 44 + (lane >> 4) * 4) * 4;
    const uint32_t bBase = smem0 + BS_OFF * 4
                         + ((warpN * 16 + (lane & 7)) * 36 + ((lane >> 3) & 1) * 4) * 4;

    float acc[3][2][2][4];
    #pragma unroll
    for (int cp = 0; cp < 3; ++cp)
        #pragma unroll
        for (int mt = 0; mt < 2; ++mt)
            #pragma unroll
            for (int nt = 0; nt < 2; ++nt)
                #pragma unroll
                for (int j = 0; j < 4; ++j) acc[cp][mt][nt][j] = 0.0f;

    uint32_t fr[3][8];
    float4 rb0, rb1;

    #define GEN2(CC) do {                                                         \
        unsigned d = dsc[(CC) * 4 + h];                                           \
        int ty = d >> 12, uu = (d >> 6) & 63, v0 = d & 63;                        \
        if (ty == 0) {                                                            \
            float4 X0 = *(const float4*)(pvx + v0), X1 = *(const float4*)(pvx + v0 + 4); \
            float4 Y0 = *(const float4*)(pvy + v0), Y1 = *(const float4*)(pvy + v0 + 4); \
            float4 Z0 = *(const float4*)(pvz + v0), Z1 = *(const float4*)(pvz + v0 + 4); \
            float ax = pvx[uu], ay = pvy[uu], az = pvz[uu];                       \
            float Xv[8] = {X0.x,X0.y,X0.z,X0.w,X1.x,X1.y,X1.z,X1.w};              \
            float Yv[8] = {Y0.x,Y0.y,Y0.z,Y0.w,Y1.x,Y1.y,Y1.z,Y1.w};              \
            float Zv[8] = {Z0.x,Z0.y,Z0.z,Z0.w,Z1.x,Z1.y,Z1.z,Z1.w};              \
            _Pragma("unroll")                                                     \
            for (int i = 0; i < 8; ++i) {                                         \
                fr[0][i] = rna(ay * Zv[i] - az * Yv[i]);                          \
                fr[1][i] = rna(az * Xv[i] - ax * Zv[i]);                          \
                fr[2][i] = rna(ax * Yv[i] - ay * Xv[i]);                          \
            }                                                                     \
        } else {                                                                  \
            _Pragma("unroll")                                                     \
            for (int i = 0; i < 8; ++i) {                                         \
                fr[0][i] = 0u; fr[1][i] = 0u; fr[2][i] = 0u;                      \
            }                                                                     \
        }                                                                         \
    } while (0)

    #define STORE_A3() do {                                                       \
        _Pragma("unroll")                                                         \
        for (int cp = 0; cp < 3; ++cp) {                                          \
            float* ap = dsm + A3_OFF + cp * ABUF + row * 44 + h * 8;              \
            *(float4*)(ap)     = make_float4(u2f(fr[cp][0]), u2f(fr[cp][1]), u2f(fr[cp][2]), u2f(fr[cp][3])); \
            *(float4*)(ap + 4) = make_float4(u2f(fr[cp][4]), u2f(fr[cp][5]), u2f(fr[cp][6]), u2f(fr[cp][7])); \
        }                                                                         \
    } while (0)

    #define STORE_B2(CC) do {                                                     \
        float* bp = dsm + BS_OFF + ((CC) & 1) * BBUF + brow * 36;                 \
        *(float4*)(bp + bc * 4)       = rb0;                                      \
        *(float4*)(bp + (bc + 4) * 4) = rb1;                                      \
    } while (0)

    #define LOAD_B2(CC) do {                                                      \
        rb0 = *(const float4*)(bbase + (CC) * 32 + bc * 4);                       \
        rb1 = *(const float4*)(bbase + (CC) * 32 + (bc + 4) * 4);                 \
    } while (0)

    __syncthreads();
    LOAD_B2(0);
    GEN2(0);
    STORE_A3();
    STORE_B2(0);
    __syncthreads();

    for (int c = 0; c < 72; ++c) {
        bool more = (c + 1 < 72);
        if (more) {
            LOAD_B2(c + 1);
            GEN2(c + 1);          // into registers only (A is single-buffered)
        }
        {
            uint32_t bT = bBase + (c & 1) * (BBUF * 4);
            #pragma unroll
            for (int k8 = 0; k8 < 4; ++k8) {
                uint32_t b[2][2];
                ldm_x2(b[0], bT + k8 * 32);
                ldm_x2(b[1], bT + 8 * 36 * 4 + k8 * 32);
                #pragma unroll
                for (int cp = 0; cp < 3; ++cp) {
                    uint32_t a[2][4];
                    uint32_t aT = aBase + cp * (ABUF * 4);
                    ldm_x4(a[0], aT + k8 * 32);
                    ldm_x4(a[1], aT + 16 * 44 * 4 + k8 * 32);
                    #pragma unroll
                    for (int mt = 0; mt < 2; ++mt)
                        #pragma unroll
                        for (int nt = 0; nt < 2; ++nt)
                            mma8(acc[cp][mt][nt], a[mt], b[nt]);
                }
            }
        }
        __syncthreads();          // all warps done reading A/B of chunk c
        if (more) {
            STORE_A3();
            STORE_B2(c + 1);
            __syncthreads();      // buffers ready for chunk c+1
        }
    }

    #pragma unroll
    for (int cp = 0; cp < 3; ++cp)
        #pragma unroll
        for (int mt = 0; mt < 2; ++mt) {
            int za = z0 + warpM * 32 + mt * 16 + g;
            int zb = za + 8;
            #pragma unroll
            for (int nt = 0; nt < 2; ++nt) {
                int col = warpN * 16 + nt * 8 + q4 * 2;
                out[(size_t)za * NOUT + 256 + col * 3 + cp]       = acc[cp][mt][nt][0];
                out[(size_t)za * NOUT + 256 + (col + 1) * 3 + cp] = acc[cp][mt][nt][1];
                out[(size_t)zb * NOUT + 256 + col * 3 + cp]       = acc[cp][mt][nt][2];
                out[(size_t)zb * NOUT + 256 + (col + 1) * 3 + cp] = acc[cp][mt][nt][3];
            }
        }
    #undef GEN2
    #undef STORE_A3
    #undef STORE_B2
    #undef LOAD_B2
}

// ===================== out1 body: z-resident, 32 B-tiles, single-buffered B ===============
__device__ __forceinline__ void tgemm_body(const float* __restrict__ x,
                                           float* __restrict__ out,
                                           float* dsm, int z0) {
    const int AS_OFF = 0;                    // [64][72]
    const int VS_OFF = 4608;                 // [64][196]
    const int BS_OFF = 17152;                // [128][72] single buffer
    float* As = dsm + AS_OFF;
    float* Vs = dsm + VS_OFF;
    float* Bs = dsm + BS_OFF;

    const int tid = threadIdx.x, lane = tid & 31, wid = tid >> 5;
    const int warpM = wid & 3, warpN = wid >> 2;    // 4M x 2N
    const int g = lane >> 2, q4 = lane & 3;

    {   // stage A (rna(s)) pair-interleaved
        int r = tid >> 2, seg = tid & 3;
        int hh = seg >> 1, qq = seg & 1;
        const float* srcA = x + (size_t)(z0 + r) * 256 + hh * 32;
        float* dstA = As + r * 72 + hh * 36;
        #pragma unroll
        for (int t = 0; t < 2; ++t) {
            int je = qq * 4 + t * 2;
            float4 v0 = *(const float4*)(srcA + je * 4);
            float4 v1 = *(const float4*)(srcA + je * 4 + 4);
            *(float2*)(dstA + je * 4 + 0) = make_float2(u2f(rna(v0.x)), u2f(rna(v1.x)));
            *(float2*)(dstA + je * 4 + 2) = make_float2(u2f(rna(v0.y)), u2f(rna(v1.y)));
            *(float2*)(dstA + je * 4 + 4) = make_float2(u2f(rna(v0.z)), u2f(rna(v1.z)));
            *(float2*)(dstA + je * 4 + 6) = make_float2(u2f(rna(v0.w)), u2f(rna(v1.w)));
        }
    }
    {   // stage V vectorized
        int r = tid >> 2, vseg = tid & 3;
        const float4* srcV = (const float4*)(x + (size_t)(z0 + r) * 256 + 64);
        float4* dstV = (float4*)(Vs + r * 196);
        #pragma unroll
        for (int t = 0; t < 12; ++t)
            dstV[vseg * 12 + t] = srcV[vseg * 12 + t];
    }

    const int brow = tid >> 1, bhh = tid & 1;
    const float* bsrc0 = g_B3p + (size_t)brow * 64 + bhh * 32;
    float* bdst = Bs + brow * 72 + bhh * 36;

    float4 rg[8];
    #define LOAD_BT(IT) do {                                                      \
        const float* s = bsrc0 + (size_t)(IT) * 128 * 64;                         \
        _Pragma("unroll")                                                         \
        for (int t = 0; t < 8; ++t) rg[t] = *(const float4*)(s + t * 4);          \
    } while (0)
    #define STORE_BT() do {                                                       \
        _Pragma("unroll")                                                         \
        for (int t = 0; t < 4; ++t) {                                             \
            *(float2*)(bdst + t * 8 + 0) = make_float2(rg[2*t].x, rg[2*t+1].x);   \
            *(float2*)(bdst + t * 8 + 2) = make_float2(rg[2*t].y, rg[2*t+1].y);   \
            *(float2*)(bdst + t * 8 + 4) = make_float2(rg[2*t].z, rg[2*t+1].z);   \
            *(float2*)(bdst + t * 8 + 6) = make_float2(rg[2*t].w, rg[2*t+1].w);   \
        }                                                                         \
    } while (0)

    LOAD_BT(0);
    STORE_BT();
    __syncthreads();

    const float sc = 0.015625f;   // 1/64 == C3/sqrt(3)

    for (int it = 0; it < 32; ++it) {
        if (it + 1 < 32) LOAD_BT(it + 1);

        float acc[8][4];
        #pragma unroll
        for (int nt = 0; nt < 8; ++nt)
            #pragma unroll
            for (int j = 0; j < 4; ++j) acc[nt][j] = 0.0f;

        #pragma unroll
        for (int ch = 0; ch < 2; ++ch) {
            #pragma unroll
            for (int k8 = 0; k8 < 4; ++k8) {
                int ko = ch * 36 + k8 * 8 + q4 * 2;
                uint32_t a[4], b[8][2];
                {
                    float2 lo = *(const float2*)(As + (warpM * 16 + g) * 72 + ko);
                    float2 hi = *(const float2*)(As + (warpM * 16 + 8 + g) * 72 + ko);
                    a[0] = __float_as_uint(lo.x); a[1] = __float_as_uint(hi.x);
                    a[2] = __float_as_uint(lo.y); a[3] = __float_as_uint(hi.y);
                }
                #pragma unroll
                for (int nt = 0; nt < 8; ++nt) {
                    float2 bv = *(const float2*)(Bs + (warpN * 64 + nt * 8 + g) * 72 + ko);
                    b[nt][0] = __float_as_uint(bv.x); b[nt][1] = __float_as_uint(bv.y);
                }
                #pragma unroll
                for (int nt = 0; nt < 8; ++nt)
                    mma8(acc[nt], a, b[nt]);
            }
        }

        {
            int ra = warpM * 16 + g;
            int rb = ra + 8;
            float p[2][3] = {{0,0,0},{0,0,0}};
            #pragma unroll
            for (int nt = 0; nt < 8; ++nt) {
                int m0 = nt * 8 + q4 * 2;
                const float* va = Vs + ra * 196 + 3 * m0;
                const float* vb = Vs + rb * 196 + 3 * m0;
                float2 va01 = *(const float2*)(va);
                float2 va23 = *(const float2*)(va + 2);
                float2 va45 = *(const float2*)(va + 4);
                float2 vb01 = *(const float2*)(vb);
                float2 vb23 = *(const float2*)(vb + 2);
                float2 vb45 = *(const float2*)(vb + 4);
                float c0 = acc[nt][0], c1 = acc[nt][1];
                float d0 = acc[nt][2], d1 = acc[nt][3];
                p[0][0] += c0 * va01.x + c1 * va23.y;
                p[0][1] += c0 * va01.y + c1 * va45.x;
                p[0][2] += c0 * va23.x + c1 * va45.y;
                p[1][0] += d0 * vb01.x + d1 * vb23.y;
                p[1][1] += d0 * vb01.y + d1 * vb45.x;
                p[1][2] += d0 * vb23.x + d1 * vb45.y;
            }
            #pragma unroll
            for (int rr = 0; rr < 2; ++rr)
                #pragma unroll
                for (int k = 0; k < 3; ++k) {
                    p[rr][k] += __shfl_xor_sync(0xFFFFFFFF, p[rr][k], 1);
                    p[rr][k] += __shfl_xor_sync(0xFFFFFFFF, p[rr][k], 2);
                }
            if (q4 == 0) {
                int w = it * 2 + warpN;
                float* oa = out + (size_t)(z0 + ra) * NOUT + 64 + w * 3;
                float* ob = out + (size_t)(z0 + rb) * NOUT + 64 + w * 3;
                oa[0] = p[0][0] * sc; oa[1] = p[0][1] * sc; oa[2] = p[0][2] * sc;
                ob[0] = p[1][0] * sc; ob[1] = p[1][1] * sc; ob[2] = p[1][2] * sc;
            }
        }

        __syncthreads();
        if (it + 1 < 32) { STORE_BT(); __syncthreads(); }
    }
    #undef LOAD_BT
    #undef STORE_BT
}

// ===================== fused kernel: one grid, longest CTAs first =====================
// bx 0..127   : out2 (z-tile bx, 64z, ALL 3 components)       ~longest
// bx 128..255 : out1 (z-tile bx-128, 64z)
// bx 256..511 : out0 (z-tile (bx-256)&127, K-split (bx-256)>>7, split-K 2)
__global__ __launch_bounds__(256) void fused_kernel(const float* __restrict__ x,
                                                    float* __restrict__ out) {
    extern __shared__ __align__(16) float dsm[];
    int bx = blockIdx.x;
    if (bx < 128) {
        out2_body(x, out, dsm, bx * 64);
    } else if (bx < 256) {
        tgemm_body(x, out, dsm, (bx - 128) * 64);
    } else {
        int idx = bx - 256;
        out0_body(x, out, dsm, (idx & 127) * 64, idx >> 7);
    }
}

// ===================== launch =====================
extern "C" void kernel_launch(void* const* d_in, const int* in_sizes, int n_in,
                              void* d_out, int out_size) {
    const float* x  = (const float*)d_in[0];
    const float* w1 = (const float*)d_in[1];
    const float* w2 = (const float*)d_in[2];
    const float* w3 = (const float*)d_in[3];
    const float* w4 = (const float*)d_in[4];
    const float* w5 = (const float*)d_in[5];
    const float* w6 = (const float*)d_in[6];
    float* out = (float*)d_out;

    float c1  = (float)sqrt(1.0 / 4160.0);     // C1
    float c2  = (float)sqrt(1.0 / 12480.0);    // C2 == C4/sqrt(3)
    float c5s = (float)sqrt(1.0 / 62400.0);    // C5/sqrt(3)
    float c6s = (float)sqrt(1.0 / 4032.0);     // C6/sqrt(6)

    const int FUSED_SMEM = 27648 * 4 + NG0 * 2;   // 111,776 (out0 branch is largest)
    cudaFuncSetAttribute(fused_kernel, cudaFuncAttributeMaxDynamicSharedMemorySize, FUSED_SMEM);

    cudaMemsetAsync(d_out, 0, (size_t)out_size * sizeof(float));
    const int NTOT = 64 * K0TOT + 64 * K2TOT + 4096 * 64;
    prep_w_kernel<<<(NTOT + 255) / 256, 256>>>(w1, w2, w3, w4, w5, w6, c1, c2, c5s, c6s);

    fused_kernel<<<512, 256, FUSED_SMEM>>>(x, out);
}

// round 17
// speedup vs baseline: 1.7049x; 1.0176x over previous
#include <cuda_runtime.h>
#include <cstdint>
#include <cmath>

#define ZDIM 8192
#define NOUT 448

#define K0TOT 4736          // out0 padded K (592 groups)
#define K2TOT 2304          // out2 padded K (288 groups)
#define NG0   592
#define NG2   288

// ===================== compile-time descriptor tables =====================
struct DescTables {
    unsigned short d0[NG0];
    unsigned short d2[NG2];
};
constexpr DescTables make_tables() {
    DescTables t{};
    for (int u = 0; u < 63; ++u) {
        int B = u >> 3, r = u & 7;
        int cum = 8 * (8 * B - (B * (B - 1)) / 2) + r * (8 - B);
        int cnt = 8 - B;
        for (int k = 0; k < cnt; ++k) {
            int v0 = 8 * (B + k);
            t.d0[cum + k]       = (unsigned short)((0 << 12) | (u << 6) | v0);  // ss
            t.d0[295 + cum + k] = (unsigned short)((2 << 12) | (u << 6) | v0);  // vdot
            t.d2[cum + k]       = (unsigned short)((0 << 12) | (u << 6) | v0);  // cross
        }
    }
    for (int u = 0; u < 8; ++u) {
        t.d0[287 + u] = (unsigned short)((1 << 12) | (8 * u));   // s^2 octet
        t.d0[582 + u] = (unsigned short)((3 << 12) | (8 * u));   // |v|^2 octet
    }
    t.d0[590] = (unsigned short)(4 << 12);
    t.d0[591] = (unsigned short)(4 << 12);
    t.d2[287] = (unsigned short)(4 << 12);
    return t;
}
static __device__ constexpr DescTables g_tables = make_tables();

// ===================== device globals (no allocation) =====================
static __device__ float g_B0t[64 * K0TOT];         // out0 weights [w][k'], prescaled + tf32
static __device__ float g_B6t[64 * K2TOT];         // out2 weights [w][k'], prescaled + tf32
static __device__ float g_B3p[4096 * 64];          // out1 weights [n=(w*64+m)][u], tf32
static __device__ unsigned short g_desc0[NG0];     // gmem copies for fast smem staging
static __device__ unsigned short g_desc2[NG2];

// ===================== helpers =====================
__device__ __forceinline__ uint32_t rna(float f) {
    uint32_t r; asm("cvt.rna.tf32.f32 %0, %1;" : "=r"(r) : "f"(f)); return r;
}
__device__ __forceinline__ float u2f(uint32_t u) { return __uint_as_float(u); }
__device__ __forceinline__ uint32_t smem_u32(const void* p) {
    uint32_t a;
    asm("{ .reg .u64 t; cvta.to.shared.u64 t, %1; cvt.u32.u64 %0, t; }" : "=r"(a) : "l"(p));
    return a;
}
__device__ __forceinline__ void mma8(float* c, const uint32_t* a, const uint32_t* b) {
    asm volatile("mma.sync.aligned.m16n8k8.row.col.f32.tf32.tf32.f32 "
        "{%0,%1,%2,%3}, {%4,%5,%6,%7}, {%8,%9}, {%0,%1,%2,%3};"
        : "+f"(c[0]), "+f"(c[1]), "+f"(c[2]), "+f"(c[3])
        : "r"(a[0]), "r"(a[1]), "r"(a[2]), "r"(a[3]), "r"(b[0]), "r"(b[1]));
}
__device__ __forceinline__ void ldm_x4(uint32_t* r, uint32_t addr) {
    asm volatile("ldmatrix.sync.aligned.m8n8.x4.shared.b16 {%0,%1,%2,%3}, [%4];"
        : "=r"(r[0]), "=r"(r[1]), "=r"(r[2]), "=r"(r[3]) : "r"(addr));
}
__device__ __forceinline__ void ldm_x2(uint32_t* r, uint32_t addr) {
    asm volatile("ldmatrix.sync.aligned.m8n8.x2.shared.b16 {%0,%1}, [%2];"
        : "=r"(r[0]), "=r"(r[1]) : "r"(addr));
}
__device__ __forceinline__ int triq(int u, int v) {   // triu index, valid v>u
    return u * 63 - (u * (u - 1)) / 2 + (v - u - 1);
}

// ===================== setup kernel (weights + table copies) =====================
__global__ void prep_w_kernel(const float* __restrict__ w1, const float* __restrict__ w2,
                              const float* __restrict__ w3, const float* __restrict__ w4,
                              const float* __restrict__ w5, const float* __restrict__ w6,
                              float c1, float c2, float c5s, float c6s) {
    int i = blockIdx.x * blockDim.x + threadIdx.x;
    if (i < NG0) g_desc0[i] = g_tables.d0[i];
    if (i < NG2) g_desc2[i] = g_tables.d2[i];
    const int N0 = 64 * K0TOT, N1 = 64 * K2TOT, N2 = 4096 * 64;
    if (i < N0) {
        int w = i / K0TOT, k = i - w * K0TOT;
        unsigned d = g_tables.d0[k >> 3];
        int ty = d >> 12, u = (d >> 6) & 63, v = (d & 63) + (k & 7);
        float val = 0.0f;
        if (ty == 0)      { if (v > u) val = c1  * w1[triq(u, v) * 64 + w]; }
        else if (ty == 1) { val = c2  * w2[v * 64 + w]; }
        else if (ty == 2) { if (v > u) val = c2  * w4[triq(u, v) * 64 + w]; }
        else if (ty == 3) { val = c5s * w5[v * 64 + w]; }
        g_B0t[i] = u2f(rna(val));
    } else if (i < N0 + N1) {
        int j = i - N0;
        int w = j / K2TOT, k = j - w * K2TOT;
        unsigned d = g_tables.d2[k >> 3];
        int ty = d >> 12, u = (d >> 6) & 63, v = (d & 63) + (k & 7);
        float val = 0.0f;
        if (ty == 0 && v > u) val = c6s * w6[triq(u, v) * 64 + w];
        g_B6t[j] = u2f(rna(val));
    } else if (i < N0 + N1 + N2) {
        int j = i - N0 - N1;
        int n = j >> 6, u = j & 63;                  // n = w*64 + m
        int w = n >> 6, m = n & 63;
        g_B3p[j] = u2f(rna(w3[(size_t)u * 4096 + m * 64 + w]));
    }
}

// ===================== out0 body: 64z x 64w CTA, KC=32 chunks, split-K 2 ==================
__device__ __forceinline__ void out0_body(const float* __restrict__ x,
                                          float* __restrict__ out,
                                          float* dsm, int z0, int y) {
    const int AS_OFF = 0;        const int ABUF = 64 * 44;    // 2816
    const int BS_OFF = 5632;     const int BBUF = 64 * 36;    // 2304
    const int S_OFF  = 10240;
    const int VX_OFF = 14592;
    const int VY_OFF = 18944;
    const int VZ_OFF = 23296;
    const int DSC_OFF = 27648;
    unsigned short* dsc = (unsigned short*)(dsm + DSC_OFF);

    const int tid = threadIdx.x, lane = tid & 31, wid = tid >> 5;
    const int warpM = wid & 1, warpN = wid >> 1;     // 2M x 4N
    const int g = lane >> 2, q4 = lane & 3;

    const int NCH = 74;
    const int kofs = y * 2368;
    const int gbase = kofs >> 3;

    // ---- stage x tile SoA + descriptor table ----
    {
        int col = tid;
        int c = col - 64;
        int m = (c >= 0) ? (c / 3) : 0;
        int k3 = c - m * 3;
        int dstoff;
        if (col < 64)       dstoff = S_OFF + col;
        else if (k3 == 0)   dstoff = VX_OFF + m;
        else if (k3 == 1)   dstoff = VY_OFF + m;
        else                dstoff = VZ_OFF + m;
        #pragma unroll 4
        for (int j = 0; j < 64; ++j)
            dsm[dstoff + j * 68] = x[(size_t)(z0 + j) * 256 + col];
    }
    for (int i = tid; i < NG0; i += 256) dsc[i] = g_desc0[i];

    const int row = tid >> 2, h = tid & 3;           // 64 rows x 4 groups/chunk
    const float* Sp  = dsm + S_OFF  + row * 68;
    const float* pvx = dsm + VX_OFF + row * 68;
    const float* pvy = dsm + VY_OFF + row * 68;
    const float* pvz = dsm + VZ_OFF + row * 68;
    const int brow = tid >> 2, bc = tid & 3;         // B stage: 64 rows, 2 float4 each
    const float* bbase = g_B0t + (size_t)brow * K0TOT + kofs;

    const uint32_t smem0 = smem_u32(dsm);
    const uint32_t aBase = smem0 + ((warpM * 32 + (lane & 15)) * 44 + (lane >> 4) * 4) * 4;
    const uint32_t bBase = smem0 + BS_OFF * 4
                         + ((warpN * 16 + (lane & 7)) * 36 + ((lane >> 3) & 1) * 4) * 4;

    float acc[2][2][4];
    #pragma unroll
    for (int mt = 0; mt < 2; ++mt)
        #pragma unroll
        for (int nt = 0; nt < 2; ++nt)
            #pragma unroll
            for (int j = 0; j < 4; ++j) acc[mt][nt][j] = 0.0f;

    uint32_t fr[8];
    float4 rb0, rb1;

    #define GEN(CC) do {                                                          \
        unsigned d = dsc[gbase + (CC) * 4 + h];                                   \
        int ty = d >> 12, uu = (d >> 6) & 63, v0 = d & 63;                        \
        float f[8];                                                               \
        if (ty <= 1) {                                                            \
            float4 p  = *(const float4*)(Sp + v0);                                \
            float4 p2 = *(const float4*)(Sp + v0 + 4);                            \
            if (ty == 0) {                                                        \
                float su = Sp[uu];                                                \
                f[0]=su*p.x;  f[1]=su*p.y;  f[2]=su*p.z;  f[3]=su*p.w;            \
                f[4]=su*p2.x; f[5]=su*p2.y; f[6]=su*p2.z; f[7]=su*p2.w;           \
            } else {                                                              \
                f[0]=p.x*p.x;   f[1]=p.y*p.y;   f[2]=p.z*p.z;   f[3]=p.w*p.w;     \
                f[4]=p2.x*p2.x; f[5]=p2.y*p2.y; f[6]=p2.z*p2.z; f[7]=p2.w*p2.w;   \
            }                                                                     \
        } else if (ty <= 3) {                                                     \
            float4 xa = *(const float4*)(pvx + v0), xb = *(const float4*)(pvx + v0 + 4); \
            float4 ya = *(const float4*)(pvy + v0), yb = *(const float4*)(pvy + v0 + 4); \
            float4 za = *(const float4*)(pvz + v0), zb = *(const float4*)(pvz + v0 + 4); \
            if (ty == 2) {                                                        \
                float ax = pvx[uu], ay = pvy[uu], az = pvz[uu];                   \
                f[0]=ax*xa.x+ay*ya.x+az*za.x; f[1]=ax*xa.y+ay*ya.y+az*za.y;       \
                f[2]=ax*xa.z+ay*ya.z+az*za.z; f[3]=ax*xa.w+ay*ya.w+az*za.w;       \
                f[4]=ax*xb.x+ay*yb.x+az*zb.x; f[5]=ax*xb.y+ay*yb.y+az*zb.y;       \
                f[6]=ax*xb.z+ay*yb.z+az*zb.z; f[7]=ax*xb.w+ay*yb.w+az*zb.w;       \
            } else {                                                              \
                f[0]=xa.x*xa.x+ya.x*ya.x+za.x*za.x; f[1]=xa.y*xa.y+ya.y*ya.y+za.y*za.y; \
                f[2]=xa.z*xa.z+ya.z*ya.z+za.z*za.z; f[3]=xa.w*xa.w+ya.w*ya.w+za.w*za.w; \
                f[4]=xb.x*xb.x+yb.x*yb.x+zb.x*zb.x; f[5]=xb.y*xb.y+yb.y*yb.y+zb.y*zb.y; \
                f[6]=xb.z*xb.z+yb.z*yb.z+zb.z*zb.z; f[7]=xb.w*xb.w+yb.w*yb.w+zb.w*zb.w; \
            }                                                                     \
        } else {                                                                  \
            _Pragma("unroll")                                                     \
            for (int i = 0; i < 8; ++i) f[i] = 0.0f;                              \
        }                                                                         \
        _Pragma("unroll")                                                         \
        for (int i = 0; i < 8; ++i) fr[i] = rna(f[i]);                            \
    } while (0)

    #define STORE_A(CC) do {                                                      \
        float* ap = dsm + AS_OFF + ((CC) & 1) * ABUF + row * 44 + h * 8;          \
        *(float4*)(ap)     = make_float4(u2f(fr[0]), u2f(fr[1]), u2f(fr[2]), u2f(fr[3])); \
        *(float4*)(ap + 4) = make_float4(u2f(fr[4]), u2f(fr[5]), u2f(fr[6]), u2f(fr[7])); \
    } while (0)

    #define STORE_B(CC) do {                                                      \
        float* bp = dsm + BS_OFF + ((CC) & 1) * BBUF + brow * 36;                 \
        *(float4*)(bp + bc * 4)       = rb0;                                      \
        *(float4*)(bp + (bc + 4) * 4) = rb1;                                      \
    } while (0)

    #define LOAD_B(CC) do {                                                       \
        rb0 = *(const float4*)(bbase + (CC) * 32 + bc * 4);                       \
        rb1 = *(const float4*)(bbase + (CC) * 32 + (bc + 4) * 4);                 \
    } while (0)

    __syncthreads();
    LOAD_B(0);
    GEN(0);
    STORE_A(0);
    STORE_B(0);
    __syncthreads();

    for (int c = 0; c < NCH; ++c) {
        bool more = (c + 1 < NCH);
        if (more) {
            LOAD_B(c + 1);
            GEN(c + 1);
            STORE_A(c + 1);
        }
        {
            uint32_t aT = aBase + (c & 1) * (ABUF * 4);
            uint32_t bT = bBase + (c & 1) * (BBUF * 4);
            #pragma unroll
            for (int k8 = 0; k8 < 4; ++k8) {
                uint32_t a[2][4], b[2][2];
                ldm_x4(a[0], aT + k8 * 32);
                ldm_x4(a[1], aT + 16 * 44 * 4 + k8 * 32);
                ldm_x2(b[0], bT + k8 * 32);
                ldm_x2(b[1], bT + 8 * 36 * 4 + k8 * 32);
                #pragma unroll
                for (int mt = 0; mt < 2; ++mt)
                    #pragma unroll
                    for (int nt = 0; nt < 2; ++nt)
                        mma8(acc[mt][nt], a[mt], b[nt]);
            }
        }
        if (more) STORE_B(c + 1);
        __syncthreads();
    }

    #pragma unroll
    for (int mt = 0; mt < 2; ++mt) {
        int za = z0 + warpM * 32 + mt * 16 + g;
        int zb = za + 8;
        #pragma unroll
        for (int nt = 0; nt < 2; ++nt) {
            int col = warpN * 16 + nt * 8 + q4 * 2;
            atomicAdd(out + (size_t)za * NOUT + col,     acc[mt][nt][0]);
            atomicAdd(out + (size_t)za * NOUT + col + 1, acc[mt][nt][1]);
            atomicAdd(out + (size_t)zb * NOUT + col,     acc[mt][nt][2]);
            atomicAdd(out + (size_t)zb * NOUT + col + 1, acc[mt][nt][3]);
        }
    }
    #undef GEN
    #undef STORE_A
    #undef STORE_B
    #undef LOAD_B
}

// ===================== out2 body: 64z CTA, ALL 3 components, 4M x 2N warps ================
// Warp tile 16M x 32N: A frag redundancy 2x (was 4x), B packed as ldm_x4 pairs shared
// across components. Single-buffered A (3 tiles), double-buffered B, 2 syncs/chunk.
__device__ __forceinline__ void out2_body(const float* __restrict__ x,
                                          float* __restrict__ out,
                                          float* dsm, int z0) {
    const int A3_OFF = 0;      const int ABUF = 64 * 44;     // 2816 floats per comp
    const int BS_OFF = 8448;   const int BBUF = 64 * 36;     // 2304 floats
    const int VX_OFF = 13056;                                // [64][68]
    const int VY_OFF = 17408;
    const int VZ_OFF = 21760;
    const int DSC_OFF = 26112;
    unsigned short* dsc = (unsigned short*)(dsm + DSC_OFF);

    const int tid = threadIdx.x, lane = tid & 31, wid = tid >> 5;
    const int warpM = wid & 3, warpN = wid >> 2;     // 4M x 2N
    const int g = lane >> 2, q4 = lane & 3;

    // ---- stage v planes ----
    if (tid >= 64) {
        int c = tid - 64;
        int m = c / 3, k3 = c - m * 3;
        int dstoff = ((k3 == 0) ? VX_OFF : (k3 == 1) ? VY_OFF : VZ_OFF) + m;
        #pragma unroll 4
        for (int j = 0; j < 64; ++j)
            dsm[dstoff + j * 68] = x[(size_t)(z0 + j) * 256 + tid];
    }
    for (int i = tid; i < NG2; i += 256) dsc[i] = g_desc2[i];

    const int row = tid >> 2, h = tid & 3;           // 64 rows x 4 groups/chunk
    const float* pvx = dsm + VX_OFF + row * 68;
    const float* pvy = dsm + VY_OFF + row * 68;
    const float* pvz = dsm + VZ_OFF + row * 68;
    const int brow = tid >> 2, bc = tid & 3;
    const float* bbase = g_B6t + (size_t)brow * K2TOT;

    const uint32_t smem0 = smem_u32(dsm);
    // A: m16 frag base (rows warpM*16 .. +15)
    const uint32_t aBase = smem0 + ((warpM * 16 + (lane & 15)) * 44 + (lane >> 4) * 4) * 4;
    // B: x4 base covering 2 n8 blocks x 2 k-halves (rows warpN*32 + (lane>>4)*8 + (lane&7))
    const uint32_t bBase = smem0 + BS_OFF * 4
                         + ((warpN * 32 + (lane >> 4) * 8 + (lane & 7)) * 36
                            + ((lane >> 3) & 1) * 4) * 4;

    float acc[3][4][4];
    #pragma unroll
    for (int cp = 0; cp < 3; ++cp)
        #pragma unroll
        for (int nt = 0; nt < 4; ++nt)
            #pragma unroll
            for (int j = 0; j < 4; ++j) acc[cp][nt][j] = 0.0f;

    uint32_t fr[3][8];
    float4 rb0, rb1;

    #define GEN2(CC) do {                                                         \
        unsigned d = dsc[(CC) * 4 + h];                                           \
        int ty = d >> 12, uu = (d >> 6) & 63, v0 = d & 63;                        \
        if (ty == 0) {                                                            \
            float4 X0 = *(const float4*)(pvx + v0), X1 = *(const float4*)(pvx + v0 + 4); \
            float4 Y0 = *(const float4*)(pvy + v0), Y1 = *(const float4*)(pvy + v0 + 4); \
            float4 Z0 = *(const float4*)(pvz + v0), Z1 = *(const float4*)(pvz + v0 + 4); \
            float ax = pvx[uu], ay = pvy[uu], az = pvz[uu];                       \
            float Xv[8] = {X0.x,X0.y,X0.z,X0.w,X1.x,X1.y,X1.z,X1.w};              \
            float Yv[8] = {Y0.x,Y0.y,Y0.z,Y0.w,Y1.x,Y1.y,Y1.z,Y1.w};              \
            float Zv[8] = {Z0.x,Z0.y,Z0.z,Z0.w,Z1.x,Z1.y,Z1.z,Z1.w};              \
            _Pragma("unroll")                                                     \
            for (int i = 0; i < 8; ++i) {                                         \
                fr[0][i] = rna(ay * Zv[i] - az * Yv[i]);                          \
                fr[1][i] = rna(az * Xv[i] - ax * Zv[i]);                          \
                fr[2][i] = rna(ax * Yv[i] - ay * Xv[i]);                          \
            }                                                                     \
        } else {                                                                  \
            _Pragma("unroll")                                                     \
            for (int i = 0; i < 8; ++i) {                                         \
                fr[0][i] = 0u; fr[1][i] = 0u; fr[2][i] = 0u;                      \
            }                                                                     \
        }                                                                         \
    } while (0)

    #define STORE_A3() do {                                                       \
        _Pragma("unroll")                                                         \
        for (int cp = 0; cp < 3; ++cp) {                                          \
            float* ap = dsm + A3_OFF + cp * ABUF + row * 44 + h * 8;              \
            *(float4*)(ap)     = make_float4(u2f(fr[cp][0]), u2f(fr[cp][1]), u2f(fr[cp][2]), u2f(fr[cp][3])); \
            *(float4*)(ap + 4) = make_float4(u2f(fr[cp][4]), u2f(fr[cp][5]), u2f(fr[cp][6]), u2f(fr[cp][7])); \
        }                                                                         \
    } while (0)

    #define STORE_B2(CC) do {                                                     \
        float* bp = dsm + BS_OFF + ((CC) & 1) * BBUF + brow * 36;                 \
        *(float4*)(bp + bc * 4)       = rb0;                                      \
        *(float4*)(bp + (bc + 4) * 4) = rb1;                                      \
    } while (0)

    #define LOAD_B2(CC) do {                                                      \
        rb0 = *(const float4*)(bbase + (CC) * 32 + bc * 4);                       \
        rb1 = *(const float4*)(bbase + (CC) * 32 + (bc + 4) * 4);                 \
    } while (0)

    __syncthreads();
    LOAD_B2(0);
    GEN2(0);
    STORE_A3();
    STORE_B2(0);
    __syncthreads();

    for (int c = 0; c < 72; ++c) {
        bool more = (c + 1 < 72);
        if (more) {
            LOAD_B2(c + 1);
            GEN2(c + 1);          // into registers only (A is single-buffered)
        }
        {
            uint32_t bT = bBase + (c & 1) * (BBUF * 4);
            #pragma unroll
            for (int k8 = 0; k8 < 4; ++k8) {
                uint32_t b[4][2];
                ldm_x4(&b[0][0], bT + k8 * 32);                   // n8 blocks 0,1
                ldm_x4(&b[2][0], bT + 16 * 36 * 4 + k8 * 32);     // n8 blocks 2,3
                #pragma unroll
                for (int cp = 0; cp < 3; ++cp) {
                    uint32_t a[4];
                    ldm_x4(a, aBase + cp * (ABUF * 4) + k8 * 32);
                    #pragma unroll
                    for (int nt = 0; nt < 4; ++nt)
                        mma8(acc[cp][nt], a, b[nt]);
                }
            }
        }
        __syncthreads();          // all warps done reading A/B of chunk c
        if (more) {
            STORE_A3();
            STORE_B2(c + 1);
            __syncthreads();      // buffers ready for chunk c+1
        }
    }

    #pragma unroll
    for (int cp = 0; cp < 3; ++cp) {
        int za = z0 + warpM * 16 + g;
        int zb = za + 8;
        #pragma unroll
        for (int nt = 0; nt < 4; ++nt) {
            int col = warpN * 32 + nt * 8 + q4 * 2;
            out[(size_t)za * NOUT + 256 + col * 3 + cp]       = acc[cp][nt][0];
            out[(size_t)za * NOUT + 256 + (col + 1) * 3 + cp] = acc[cp][nt][1];
            out[(size_t)zb * NOUT + 256 + col * 3 + cp]       = acc[cp][nt][2];
            out[(size_t)zb * NOUT + 256 + (col + 1) * 3 + cp] = acc[cp][nt][3];
        }
    }
    #undef GEN2
    #undef STORE_A3
    #undef STORE_B2
    #undef LOAD_B2
}

// ===================== out1 body: z-resident, 32 B-tiles, single-buffered B ===============
__device__ __forceinline__ void tgemm_body(const float* __restrict__ x,
                                           float* __restrict__ out,
                                           float* dsm, int z0) {
    const int AS_OFF = 0;                    // [64][72]
    const int VS_OFF = 4608;                 // [64][196]
    const int BS_OFF = 17152;                // [128][72] single buffer
    float* As = dsm + AS_OFF;
    float* Vs = dsm + VS_OFF;
    float* Bs = dsm + BS_OFF;

    const int tid = threadIdx.x, lane = tid & 31, wid = tid >> 5;
    const int warpM = wid & 3, warpN = wid >> 2;    // 4M x 2N
    const int g = lane >> 2, q4 = lane & 3;

    {   // stage A (rna(s)) pair-interleaved
        int r = tid >> 2, seg = tid & 3;
        int hh = seg >> 1, qq = seg & 1;
        const float* srcA = x + (size_t)(z0 + r) * 256 + hh * 32;
        float* dstA = As + r * 72 + hh * 36;
        #pragma unroll
        for (int t = 0; t < 2; ++t) {
            int je = qq * 4 + t * 2;
            float4 v0 = *(const float4*)(srcA + je * 4);
            float4 v1 = *(const float4*)(srcA + je * 4 + 4);
            *(float2*)(dstA + je * 4 + 0) = make_float2(u2f(rna(v0.x)), u2f(rna(v1.x)));
            *(float2*)(dstA + je * 4 + 2) = make_float2(u2f(rna(v0.y)), u2f(rna(v1.y)));
            *(float2*)(dstA + je * 4 + 4) = make_float2(u2f(rna(v0.z)), u2f(rna(v1.z)));
            *(float2*)(dstA + je * 4 + 6) = make_float2(u2f(rna(v0.w)), u2f(rna(v1.w)));
        }
    }
    {   // stage V vectorized
        int r = tid >> 2, vseg = tid & 3;
        const float4* srcV = (const float4*)(x + (size_t)(z0 + r) * 256 + 64);
        float4* dstV = (float4*)(Vs + r * 196);
        #pragma unroll
        for (int t = 0; t < 12; ++t)
            dstV[vseg * 12 + t] = srcV[vseg * 12 + t];
    }

    const int brow = tid >> 1, bhh = tid & 1;
    const float* bsrc0 = g_B3p + (size_t)brow * 64 + bhh * 32;
    float* bdst = Bs + brow * 72 + bhh * 36;

    float4 rg[8];
    #define LOAD_BT(IT) do {                                                      \
        const float* s = bsrc0 + (size_t)(IT) * 128 * 64;                         \
        _Pragma("unroll")                                                         \
        for (int t = 0; t < 8; ++t) rg[t] = *(const float4*)(s + t * 4);          \
    } while (0)
    #define STORE_BT() do {                                                       \
        _Pragma("unroll")                                                         \
        for (int t = 0; t < 4; ++t) {                                             \
            *(float2*)(bdst + t * 8 + 0) = make_float2(rg[2*t].x, rg[2*t+1].x);   \
            *(float2*)(bdst + t * 8 + 2) = make_float2(rg[2*t].y, rg[2*t+1].y);   \
            *(float2*)(bdst + t * 8 + 4) = make_float2(rg[2*t].z, rg[2*t+1].z);   \
            *(float2*)(bdst + t * 8 + 6) = make_float2(rg[2*t].w, rg[2*t+1].w);   \
        }                                                                         \
    } while (0)

    LOAD_BT(0);
    STORE_BT();
    __syncthreads();

    const float sc = 0.015625f;   // 1/64 == C3/sqrt(3)

    for (int it = 0; it < 32; ++it) {
        if (it + 1 < 32) LOAD_BT(it + 1);

        float acc[8][4];
        #pragma unroll
        for (int nt = 0; nt < 8; ++nt)
            #pragma unroll
            for (int j = 0; j < 4; ++j) acc[nt][j] = 0.0f;

        #pragma unroll
        for (int ch = 0; ch < 2; ++ch) {
            #pragma unroll
            for (int k8 = 0; k8 < 4; ++k8) {
                int ko = ch * 36 + k8 * 8 + q4 * 2;
                uint32_t a[4], b[8][2];
                {
                    float2 lo = *(const float2*)(As + (warpM * 16 + g) * 72 + ko);
                    float2 hi = *(const float2*)(As + (warpM * 16 + 8 + g) * 72 + ko);
                    a[0] = __float_as_uint(lo.x); a[1] = __float_as_uint(hi.x);
                    a[2] = __float_as_uint(lo.y); a[3] = __float_as_uint(hi.y);
                }
                #pragma unroll
                for (int nt = 0; nt < 8; ++nt) {
                    float2 bv = *(const float2*)(Bs + (warpN * 64 + nt * 8 + g) * 72 + ko);
                    b[nt][0] = __float_as_uint(bv.x); b[nt][1] = __float_as_uint(bv.y);
                }
                #pragma unroll
                for (int nt = 0; nt < 8; ++nt)
                    mma8(acc[nt], a, b[nt]);
            }
        }

        {
            int ra = warpM * 16 + g;
            int rb = ra + 8;
            float p[2][3] = {{0,0,0},{0,0,0}};
            #pragma unroll
            for (int nt = 0; nt < 8; ++nt) {
                int m0 = nt * 8 + q4 * 2;
                const float* va = Vs + ra * 196 + 3 * m0;
                const float* vb = Vs + rb * 196 + 3 * m0;
                float2 va01 = *(const float2*)(va);
                float2 va23 = *(const float2*)(va + 2);
                float2 va45 = *(const float2*)(va + 4);
                float2 vb01 = *(const float2*)(vb);
                float2 vb23 = *(const float2*)(vb + 2);
                float2 vb45 = *(const float2*)(vb + 4);
                float c0 = acc[nt][0], c1 = acc[nt][1];
                float d0 = acc[nt][2], d1 = acc[nt][3];
                p[0][0] += c0 * va01.x + c1 * va23.y;
                p[0][1] += c0 * va01.y + c1 * va45.x;
                p[0][2] += c0 * va23.x + c1 * va45.y;
                p[1][0] += d0 * vb01.x + d1 * vb23.y;
                p[1][1] += d0 * vb01.y + d1 * vb45.x;
                p[1][2] += d0 * vb23.x + d1 * vb45.y;
            }
            #pragma unroll
            for (int rr = 0; rr < 2; ++rr)
                #pragma unroll
                for (int k = 0; k < 3; ++k) {
                    p[rr][k] += __shfl_xor_sync(0xFFFFFFFF, p[rr][k], 1);
                    p[rr][k] += __shfl_xor_sync(0xFFFFFFFF, p[rr][k], 2);
                }
            if (q4 == 0) {
                int w = it * 2 + warpN;
                float* oa = out + (size_t)(z0 + ra) * NOUT + 64 + w * 3;
                float* ob = out + (size_t)(z0 + rb) * NOUT + 64 + w * 3;
                oa[0] = p[0][0] * sc; oa[1] = p[0][1] * sc; oa[2] = p[0][2] * sc;
                ob[0] = p[1][0] * sc; ob[1] = p[1][1] * sc; ob[2] = p[1][2] * sc;
            }
        }

        __syncthreads();
        if (it + 1 < 32) { STORE_BT(); __syncthreads(); }
    }
    #undef LOAD_BT
    #undef STORE_BT
}

// ===================== fused kernel: one grid, longest CTAs first =====================
// bx 0..127   : out2 (z-tile bx, 64z, ALL 3 components)       ~longest
// bx 128..255 : out1 (z-tile bx-128, 64z)
// bx 256..511 : out0 (z-tile (bx-256)&127, K-split (bx-256)>>7, split-K 2)
__global__ __launch_bounds__(256) void fused_kernel(const float* __restrict__ x,
                                                    float* __restrict__ out) {
    extern __shared__ __align__(16) float dsm[];
    int bx = blockIdx.x;
    if (bx < 128) {
        out2_body(x, out, dsm, bx * 64);
    } else if (bx < 256) {
        tgemm_body(x, out, dsm, (bx - 128) * 64);
    } else {
        int idx = bx - 256;
        out0_body(x, out, dsm, (idx & 127) * 64, idx >> 7);
    }
}

// ===================== launch =====================
extern "C" void kernel_launch(void* const* d_in, const int* in_sizes, int n_in,
                              void* d_out, int out_size) {
    const float* x  = (const float*)d_in[0];
    const float* w1 = (const float*)d_in[1];
    const float* w2 = (const float*)d_in[2];
    const float* w3 = (const float*)d_in[3];
    const float* w4 = (const float*)d_in[4];
    const float* w5 = (const float*)d_in[5];
    const float* w6 = (const float*)d_in[6];
    float* out = (float*)d_out;

    float c1  = (float)sqrt(1.0 / 4160.0);     // C1
    float c2  = (float)sqrt(1.0 / 12480.0);    // C2 == C4/sqrt(3)
    float c5s = (float)sqrt(1.0 / 62400.0);    // C5/sqrt(3)
    float c6s = (float)sqrt(1.0 / 4032.0);     // C6/sqrt(6)

    const int FUSED_SMEM = 27648 * 4 + NG0 * 2;   // 111,776 (out0 branch is largest)
    cudaFuncSetAttribute(fused_kernel, cudaFuncAttributeMaxDynamicSharedMemorySize, FUSED_SMEM);

    cudaMemsetAsync(d_out, 0, (size_t)out_size * sizeof(float));
    const int NTOT = 64 * K0TOT + 64 * K2TOT + 4096 * 64;
    prep_w_kernel<<<(NTOT + 255) / 256, 256>>>(w1, w2, w3, w4, w5, w6, c1, c2, c5s, c6s);

    fused_kernel<<<512, 256, FUSED_SMEM>>>(x, out);
}